// round 1
// baseline (speedup 1.0000x reference)
#include <cuda_runtime.h>
#include <math.h>

#define BS      256
#define HID     1024
#define ACT     16
#define MEM_DIM 512
#define NUM_MEM 1024

// Output layout (tuple concat): read_v | other_v | M_new | alpha
#define OUT_READV 0
#define OUT_OTHER (BS * MEM_DIM)                       // 131072
#define OUT_MNEW  (2 * BS * MEM_DIM)                   // 262144
#define OUT_ALPHA (2 * BS * MEM_DIM + BS * NUM_MEM * MEM_DIM)  // 134479872

// ---------------- scratch (device globals; no allocation allowed) ----------
__device__ __align__(16) float g_kern[BS * 9];
__device__ __align__(16) float g_G1[BS * MEM_DIM];
__device__ __align__(16) float g_gate[BS];
__device__ __align__(16) float g_erase[BS * MEM_DIM];
__device__ __align__(16) float g_add[BS * MEM_DIM];

__device__ __forceinline__ float leakyf(float x) { return x > 0.f ? x : 0.2f * x; }
__device__ __forceinline__ float sigmoidf_(float x) { return 1.f / (1.f + expf(-x)); }

// ---------------- kernel 1: kernel-net + flip + softmax --------------------
__global__ void kernelnet_kernel(const float* __restrict__ A,
                                 const float* __restrict__ Wk1,
                                 const float* __restrict__ bk1,
                                 const float* __restrict__ Wk2,
                                 const float* __restrict__ bk2) {
    int b = blockIdx.x;
    int tid = threadIdx.x;  // 512 threads
    __shared__ float sa[ACT], sna[ACT];
    __shared__ float k1[MEM_DIM], k1b[MEM_DIM];
    __shared__ float kk[9], kkb[9];
    __shared__ int sm_flag;

    if (tid < ACT) {
        float v = A[b * ACT + tid];
        sa[tid] = v;
        sna[tid] = v;
    }
    __syncthreads();
    if (tid == 0) {
        int am = 0;
        float best = sa[0];
        for (int i = 1; i < ACT; i++)
            if (sa[i] > best) { best = sa[i]; am = i; }
        int m = (am == 0);
        sm_flag = m;
        if (m) { sna[0] = 0.f; sna[1] = 1.f; }
    }
    __syncthreads();

    {
        float x = bk1[tid], xb = x;
        #pragma unroll
        for (int i = 0; i < ACT; i++) {
            float w = Wk1[i * MEM_DIM + tid];
            x = fmaf(sa[i], w, x);
            xb = fmaf(sna[i], w, xb);
        }
        k1[tid] = leakyf(x);
        k1b[tid] = leakyf(xb);
    }
    __syncthreads();
    if (tid < 9) {
        float s = bk2[tid], sb = s;
        for (int j = 0; j < MEM_DIM; j++) {
            float w = Wk2[j * 9 + tid];
            s = fmaf(k1[j], w, s);
            sb = fmaf(k1b[j], w, sb);
        }
        kk[tid] = s;
        kkb[tid] = sb;
    }
    __syncthreads();
    if (tid == 0) {
        float v[9];
        int m = sm_flag;
        #pragma unroll
        for (int i = 0; i < 9; i++) v[i] = m ? kkb[8 - i] : kk[i];
        float mx = v[0];
        #pragma unroll
        for (int i = 1; i < 9; i++) mx = fmaxf(mx, v[i]);
        float sum = 0.f;
        #pragma unroll
        for (int i = 0; i < 9; i++) { v[i] = expf(v[i] - mx); sum += v[i]; }
        float inv = 1.f / sum;
        #pragma unroll
        for (int i = 0; i < 9; i++) g_kern[b * 9 + i] = v[i] * inv;
    }
}

// ---------------- kernel 2: fused SGEMM h @ [Wv | Wg1] ---------------------
// M=256, N=2048 (1536 Wv + 512 Wg1), K=1024. BM=BN=64, BK=16, 256 thr, 4x4.
__global__ void gemm_kernel(const float* __restrict__ H,
                            const float* __restrict__ Wv,
                            const float* __restrict__ bv,
                            const float* __restrict__ Wg1,
                            const float* __restrict__ bg1,
                            float* __restrict__ out_other) {
    const int n0 = blockIdx.x * 64;
    const int m0 = blockIdx.y * 64;
    const bool isG = (n0 >= 3 * MEM_DIM);
    const float* W = isG ? Wg1 : Wv;
    const int ldw = isG ? MEM_DIM : 3 * MEM_DIM;
    const int ncol0 = isG ? (n0 - 3 * MEM_DIM) : n0;

    __shared__ __align__(16) float As[16][64];
    __shared__ __align__(16) float Bs[16][64];

    int tid = threadIdx.x;
    int tx = tid & 15, ty = tid >> 4;
    int a_m = tid >> 2;
    int a_k = (tid & 3) * 4;
    int b_k = tid >> 4;
    int b_n = (tid & 15) * 4;

    float acc[4][4] = {};

    for (int k0 = 0; k0 < HID; k0 += 16) {
        float4 av = *(const float4*)(H + (size_t)(m0 + a_m) * HID + k0 + a_k);
        As[a_k + 0][a_m] = av.x;
        As[a_k + 1][a_m] = av.y;
        As[a_k + 2][a_m] = av.z;
        As[a_k + 3][a_m] = av.w;
        *(float4*)&Bs[b_k][b_n] =
            *(const float4*)(W + (size_t)(k0 + b_k) * ldw + ncol0 + b_n);
        __syncthreads();
        #pragma unroll
        for (int k = 0; k < 16; k++) {
            float4 a4 = *(const float4*)&As[k][ty * 4];
            float4 b4 = *(const float4*)&Bs[k][tx * 4];
            float ar[4] = {a4.x, a4.y, a4.z, a4.w};
            float br[4] = {b4.x, b4.y, b4.z, b4.w};
            #pragma unroll
            for (int i = 0; i < 4; i++)
                #pragma unroll
                for (int j = 0; j < 4; j++)
                    acc[i][j] = fmaf(ar[i], br[j], acc[i][j]);
        }
        __syncthreads();
    }

    #pragma unroll
    for (int i = 0; i < 4; i++) {
        int row = m0 + ty * 4 + i;
        #pragma unroll
        for (int j = 0; j < 4; j++) {
            int cc = ncol0 + tx * 4 + j;
            float val = acc[i][j];
            if (isG) {
                val += bg1[cc];
                g_G1[row * MEM_DIM + cc] = leakyf(val);
            } else {
                val += bv[cc];
                if (cc < MEM_DIM) {
                    g_erase[row * MEM_DIM + cc] = sigmoidf_(val);
                } else if (cc < 2 * MEM_DIM) {
                    g_add[row * MEM_DIM + (cc - MEM_DIM)] = val;
                } else {
                    out_other[row * MEM_DIM + (cc - 2 * MEM_DIM)] = val;
                }
            }
        }
    }
}

// ---------------- kernel 3: gate = sigmoid(G1 @ Wg2 + bg2) -----------------
__global__ void gate_kernel(const float* __restrict__ Wg2,
                            const float* __restrict__ bg2) {
    int b = blockIdx.x * 8 + threadIdx.y;
    float s = 0.f;
    for (int j = threadIdx.x; j < MEM_DIM; j += 32)
        s = fmaf(g_G1[b * MEM_DIM + j], Wg2[j], s);
    #pragma unroll
    for (int o = 16; o > 0; o >>= 1) s += __shfl_down_sync(0xffffffffu, s, o);
    if (threadIdx.x == 0) g_gate[b] = sigmoidf_(s + bg2[0]);
}

// ---------------- kernel 4: depthwise 3x3 conv + gated blend -> alpha ------
__global__ void conv_alpha_kernel(const float* __restrict__ prev_alpha,
                                  float* __restrict__ alpha_out) {
    int b = blockIdx.x;
    int tid = threadIdx.x;  // 256
    __shared__ float t[34][34];
    __shared__ float kk[9];
    float* tf = &t[0][0];
    for (int i = tid; i < 34 * 34; i += 256) tf[i] = 0.f;
    if (tid < 9) kk[tid] = g_kern[b * 9 + tid];
    __syncthreads();
    for (int i = tid; i < 1024; i += 256)
        t[1 + (i >> 5)][1 + (i & 31)] = prev_alpha[b * 1024 + i];
    __syncthreads();
    float g = g_gate[b];
    for (int i = tid; i < 1024; i += 256) {
        int y = i >> 5, x = i & 31;
        float s = 0.f;
        #pragma unroll
        for (int ky = 0; ky < 3; ky++)
            #pragma unroll
            for (int kx = 0; kx < 3; kx++)
                s = fmaf(t[y + ky][x + kx], kk[ky * 3 + kx], s);
        float pa = t[1 + y][1 + x];
        alpha_out[b * 1024 + i] = s * g + pa * (1.f - g);
    }
}

// ---------------- kernel 5: M update + fused read_v ------------------------
// grid (4, 256), 32 threads; each thread handles one float4 (4 d's).
__global__ void mupdate_kernel(const float* __restrict__ M,
                               const float* __restrict__ alpha,
                               float* __restrict__ mnew,
                               float* __restrict__ readv) {
    int b = blockIdx.y;
    int d4 = blockIdx.x * 32 + threadIdx.x;  // 0..127
    __shared__ float sal[NUM_MEM];
    for (int i = threadIdx.x; i < NUM_MEM; i += 32)
        sal[i] = alpha[b * NUM_MEM + i];
    __syncthreads();

    const float4* Mb = (const float4*)M + (size_t)b * (NUM_MEM * MEM_DIM / 4);
    float4* Ob = (float4*)mnew + (size_t)b * (NUM_MEM * MEM_DIM / 4);
    float4 e = ((const float4*)g_erase)[b * (MEM_DIM / 4) + d4];
    float4 v = ((const float4*)g_add)[b * (MEM_DIM / 4) + d4];
    float4 rv = make_float4(0.f, 0.f, 0.f, 0.f);

    #pragma unroll 8
    for (int n = 0; n < NUM_MEM; n++) {
        float a = sal[n];
        float4 m = __ldcs(&Mb[(size_t)n * 128 + d4]);
        float4 mn;
        // M_new = M + a*(v - M*e)  ==  M*(1 - a*e) + a*v
        mn.x = fmaf(a, fmaf(-m.x, e.x, v.x), m.x);
        mn.y = fmaf(a, fmaf(-m.y, e.y, v.y), m.y);
        mn.z = fmaf(a, fmaf(-m.z, e.z, v.z), m.z);
        mn.w = fmaf(a, fmaf(-m.w, e.w, v.w), m.w);
        rv.x = fmaf(a, mn.x, rv.x);
        rv.y = fmaf(a, mn.y, rv.y);
        rv.z = fmaf(a, mn.z, rv.z);
        rv.w = fmaf(a, mn.w, rv.w);
        __stcs(&Ob[(size_t)n * 128 + d4], mn);
    }
    ((float4*)readv)[b * (MEM_DIM / 4) + d4] = rv;
}

// ---------------- launch ----------------------------------------------------
extern "C" void kernel_launch(void* const* d_in, const int* in_sizes, int n_in,
                              void* d_out, int out_size) {
    const float* h          = (const float*)d_in[0];
    const float* a          = (const float*)d_in[1];
    // d_in[2] = prev_h (unused by reference outputs)
    const float* prev_alpha = (const float*)d_in[3];
    const float* M          = (const float*)d_in[4];
    const float* Wv         = (const float*)d_in[5];
    const float* bv         = (const float*)d_in[6];
    const float* Wk1        = (const float*)d_in[7];
    const float* bk1        = (const float*)d_in[8];
    const float* Wk2        = (const float*)d_in[9];
    const float* bk2        = (const float*)d_in[10];
    const float* Wg1        = (const float*)d_in[11];
    const float* bg1        = (const float*)d_in[12];
    const float* Wg2        = (const float*)d_in[13];
    const float* bg2        = (const float*)d_in[14];

    float* out = (float*)d_out;
    float* out_readv = out + OUT_READV;
    float* out_other = out + OUT_OTHER;
    float* out_mnew  = out + OUT_MNEW;
    float* out_alpha = out + OUT_ALPHA;

    kernelnet_kernel<<<BS, 512>>>(a, Wk1, bk1, Wk2, bk2);
    gemm_kernel<<<dim3(32, 4), 256>>>(h, Wv, bv, Wg1, bg1, out_other);
    gate_kernel<<<32, dim3(32, 8)>>>(Wg2, bg2);
    conv_alpha_kernel<<<BS, 256>>>(prev_alpha, out_alpha);
    mupdate_kernel<<<dim3(4, BS), 32>>>(M, out_alpha, out_mnew, out_readv);
}

// round 2
// speedup vs baseline: 2.1350x; 2.1350x over previous
#include <cuda_runtime.h>
#include <math.h>

#define BS      256
#define HID     1024
#define ACT     16
#define MEM_DIM 512
#define NUM_MEM 1024
#define NSPLIT  8
#define NCHUNK  (NUM_MEM / NSPLIT)   // 128 memory rows per block

// Output layout (tuple concat): read_v | other_v | M_new | alpha
#define OUT_READV 0
#define OUT_OTHER (BS * MEM_DIM)                       // 131072
#define OUT_MNEW  (2 * BS * MEM_DIM)                   // 262144
#define OUT_ALPHA (2 * BS * MEM_DIM + BS * NUM_MEM * MEM_DIM)  // 134479872

// ---------------- scratch (device globals; no allocation allowed) ----------
__device__ __align__(16) float g_kern[BS * 9];
__device__ __align__(16) float g_G1[BS * MEM_DIM];
__device__ __align__(16) float g_gate[BS];
__device__ __align__(16) float g_erase[BS * MEM_DIM];
__device__ __align__(16) float g_add[BS * MEM_DIM];
__device__ __align__(16) float g_rvpart[NSPLIT * BS * MEM_DIM];  // 4 MB

__device__ __forceinline__ float leakyf(float x) { return x > 0.f ? x : 0.2f * x; }
__device__ __forceinline__ float sigmoidf_(float x) { return 1.f / (1.f + expf(-x)); }

// ---------------- kernel 1: kernel-net + flip + softmax --------------------
// 512 threads: thread j owns hidden unit j; stage-2 9-dot reduced via shuffles.
__global__ void kernelnet_kernel(const float* __restrict__ A,
                                 const float* __restrict__ Wk1,
                                 const float* __restrict__ bk1,
                                 const float* __restrict__ Wk2,
                                 const float* __restrict__ bk2) {
    int b = blockIdx.x;
    int tid = threadIdx.x;  // 512
    int lane = tid & 31, wid = tid >> 5;  // 16 warps
    __shared__ float sa[ACT], sna[ACT];
    __shared__ float spart[16][9], spartb[16][9];
    __shared__ float kk[9], kkb[9];
    __shared__ int sm_flag;

    if (tid < ACT) {
        float v = A[b * ACT + tid];
        sa[tid] = v;
        sna[tid] = v;
    }
    __syncthreads();
    if (tid == 0) {
        int am = 0;
        float best = sa[0];
        for (int i = 1; i < ACT; i++)
            if (sa[i] > best) { best = sa[i]; am = i; }
        int m = (am == 0);
        sm_flag = m;
        if (m) { sna[0] = 0.f; sna[1] = 1.f; }
    }
    __syncthreads();

    // stage 1: k1 = leaky(a @ Wk1 + bk1), per-thread scalar (j = tid)
    float x = bk1[tid], xb = x;
    #pragma unroll
    for (int i = 0; i < ACT; i++) {
        float w = Wk1[i * MEM_DIM + tid];
        x = fmaf(sa[i], w, x);
        xb = fmaf(sna[i], w, xb);
    }
    x = leakyf(x);
    xb = leakyf(xb);

    // stage 2: kk[t] = sum_j k1[j] * Wk2[j*9+t]
    float p[9], pb[9];
    #pragma unroll
    for (int t = 0; t < 9; t++) {
        float w = Wk2[tid * 9 + t];
        p[t] = x * w;
        pb[t] = xb * w;
    }
    #pragma unroll
    for (int t = 0; t < 9; t++) {
        #pragma unroll
        for (int o = 16; o > 0; o >>= 1) {
            p[t] += __shfl_down_sync(0xffffffffu, p[t], o);
            pb[t] += __shfl_down_sync(0xffffffffu, pb[t], o);
        }
    }
    if (lane == 0) {
        #pragma unroll
        for (int t = 0; t < 9; t++) { spart[wid][t] = p[t]; spartb[wid][t] = pb[t]; }
    }
    __syncthreads();
    if (tid < 9) {
        float s = bk2[tid];
        #pragma unroll
        for (int w = 0; w < 16; w++) s += spart[w][tid];
        kk[tid] = s;
    } else if (tid >= 32 && tid < 41) {
        int t = tid - 32;
        float s = bk2[t];
        #pragma unroll
        for (int w = 0; w < 16; w++) s += spartb[w][t];
        kkb[t] = s;
    }
    __syncthreads();
    if (tid == 0) {
        float v[9];
        int m = sm_flag;
        #pragma unroll
        for (int i = 0; i < 9; i++) v[i] = m ? kkb[8 - i] : kk[i];
        float mx = v[0];
        #pragma unroll
        for (int i = 1; i < 9; i++) mx = fmaxf(mx, v[i]);
        float sum = 0.f;
        #pragma unroll
        for (int i = 0; i < 9; i++) { v[i] = expf(v[i] - mx); sum += v[i]; }
        float inv = 1.f / sum;
        #pragma unroll
        for (int i = 0; i < 9; i++) g_kern[b * 9 + i] = v[i] * inv;
    }
}

// ---------------- kernel 2: fused SGEMM h @ [Wv | Wg1] ---------------------
// M=256, N=2048 (1536 Wv + 512 Wg1), K=1024. BM=BN=64, BK=16, 256 thr, 4x4.
__global__ void gemm_kernel(const float* __restrict__ H,
                            const float* __restrict__ Wv,
                            const float* __restrict__ bv,
                            const float* __restrict__ Wg1,
                            const float* __restrict__ bg1,
                            float* __restrict__ out_other) {
    const int n0 = blockIdx.x * 64;
    const int m0 = blockIdx.y * 64;
    const bool isG = (n0 >= 3 * MEM_DIM);
    const float* W = isG ? Wg1 : Wv;
    const int ldw = isG ? MEM_DIM : 3 * MEM_DIM;
    const int ncol0 = isG ? (n0 - 3 * MEM_DIM) : n0;

    __shared__ __align__(16) float As[16][64];
    __shared__ __align__(16) float Bs[16][64];

    int tid = threadIdx.x;
    int tx = tid & 15, ty = tid >> 4;
    int a_m = tid >> 2;
    int a_k = (tid & 3) * 4;
    int b_k = tid >> 4;
    int b_n = (tid & 15) * 4;

    float acc[4][4] = {};

    for (int k0 = 0; k0 < HID; k0 += 16) {
        float4 av = *(const float4*)(H + (size_t)(m0 + a_m) * HID + k0 + a_k);
        As[a_k + 0][a_m] = av.x;
        As[a_k + 1][a_m] = av.y;
        As[a_k + 2][a_m] = av.z;
        As[a_k + 3][a_m] = av.w;
        *(float4*)&Bs[b_k][b_n] =
            *(const float4*)(W + (size_t)(k0 + b_k) * ldw + ncol0 + b_n);
        __syncthreads();
        #pragma unroll
        for (int k = 0; k < 16; k++) {
            float4 a4 = *(const float4*)&As[k][ty * 4];
            float4 b4 = *(const float4*)&Bs[k][tx * 4];
            float ar[4] = {a4.x, a4.y, a4.z, a4.w};
            float br[4] = {b4.x, b4.y, b4.z, b4.w};
            #pragma unroll
            for (int i = 0; i < 4; i++)
                #pragma unroll
                for (int j = 0; j < 4; j++)
                    acc[i][j] = fmaf(ar[i], br[j], acc[i][j]);
        }
        __syncthreads();
    }

    #pragma unroll
    for (int i = 0; i < 4; i++) {
        int row = m0 + ty * 4 + i;
        #pragma unroll
        for (int j = 0; j < 4; j++) {
            int cc = ncol0 + tx * 4 + j;
            float val = acc[i][j];
            if (isG) {
                val += bg1[cc];
                g_G1[row * MEM_DIM + cc] = leakyf(val);
            } else {
                val += bv[cc];
                if (cc < MEM_DIM) {
                    g_erase[row * MEM_DIM + cc] = sigmoidf_(val);
                } else if (cc < 2 * MEM_DIM) {
                    g_add[row * MEM_DIM + (cc - MEM_DIM)] = val;
                } else {
                    out_other[row * MEM_DIM + (cc - 2 * MEM_DIM)] = val;
                }
            }
        }
    }
}

// ---------------- kernel 3: gate = sigmoid(G1 @ Wg2 + bg2) -----------------
__global__ void gate_kernel(const float* __restrict__ Wg2,
                            const float* __restrict__ bg2) {
    int b = blockIdx.x * 8 + threadIdx.y;
    float s = 0.f;
    for (int j = threadIdx.x; j < MEM_DIM; j += 32)
        s = fmaf(g_G1[b * MEM_DIM + j], Wg2[j], s);
    #pragma unroll
    for (int o = 16; o > 0; o >>= 1) s += __shfl_down_sync(0xffffffffu, s, o);
    if (threadIdx.x == 0) g_gate[b] = sigmoidf_(s + bg2[0]);
}

// ---------------- kernel 4: depthwise 3x3 conv + gated blend -> alpha ------
__global__ void conv_alpha_kernel(const float* __restrict__ prev_alpha,
                                  float* __restrict__ alpha_out) {
    int b = blockIdx.x;
    int tid = threadIdx.x;  // 256
    __shared__ float t[34][34];
    __shared__ float kk[9];
    float* tf = &t[0][0];
    for (int i = tid; i < 34 * 34; i += 256) tf[i] = 0.f;
    if (tid < 9) kk[tid] = g_kern[b * 9 + tid];
    __syncthreads();
    for (int i = tid; i < 1024; i += 256)
        t[1 + (i >> 5)][1 + (i & 31)] = prev_alpha[b * 1024 + i];
    __syncthreads();
    float g = g_gate[b];
    for (int i = tid; i < 1024; i += 256) {
        int y = i >> 5, x = i & 31;
        float s = 0.f;
        #pragma unroll
        for (int ky = 0; ky < 3; ky++)
            #pragma unroll
            for (int kx = 0; kx < 3; kx++)
                s = fmaf(t[y + ky][x + kx], kk[ky * 3 + kx], s);
        float pa = t[1 + y][1 + x];
        alpha_out[b * 1024 + i] = s * g + pa * (1.f - g);
    }
}

// ---------------- kernel 5: M update + partial read_v ----------------------
// grid (NSPLIT, BS), 128 threads; thread = one float4 of MEM_DIM, loops
// over NCHUNK=128 memory rows. 2048 blocks -> ~56 warps/SM.
__global__ void mupdate_kernel(const float* __restrict__ M,
                               const float* __restrict__ alpha,
                               float* __restrict__ mnew) {
    int b = blockIdx.y;
    int c = blockIdx.x;          // n-chunk
    int d4 = threadIdx.x;        // 0..127
    __shared__ float sal[NCHUNK];
    sal[d4] = alpha[b * NUM_MEM + c * NCHUNK + d4];
    __syncthreads();

    size_t base = (size_t)b * (NUM_MEM * 128) + (size_t)c * (NCHUNK * 128);
    const float4* Mb = (const float4*)M + base;
    float4* Ob = (float4*)mnew + base;
    float4 e = ((const float4*)g_erase)[b * 128 + d4];
    float4 v = ((const float4*)g_add)[b * 128 + d4];
    float4 rv = make_float4(0.f, 0.f, 0.f, 0.f);

    #pragma unroll 8
    for (int n = 0; n < NCHUNK; n++) {
        float a = sal[n];
        float4 m = __ldcs(&Mb[n * 128 + d4]);
        float4 mn;
        // M_new = M + a*(v - M*e)
        mn.x = fmaf(a, fmaf(-m.x, e.x, v.x), m.x);
        mn.y = fmaf(a, fmaf(-m.y, e.y, v.y), m.y);
        mn.z = fmaf(a, fmaf(-m.z, e.z, v.z), m.z);
        mn.w = fmaf(a, fmaf(-m.w, e.w, v.w), m.w);
        rv.x = fmaf(a, mn.x, rv.x);
        rv.y = fmaf(a, mn.y, rv.y);
        rv.z = fmaf(a, mn.z, rv.z);
        rv.w = fmaf(a, mn.w, rv.w);
        __stcs(&Ob[n * 128 + d4], mn);
    }
    ((float4*)g_rvpart)[((size_t)c * BS + b) * 128 + d4] = rv;
}

// ---------------- kernel 6: reduce read_v partials -------------------------
__global__ void rvreduce_kernel(float* __restrict__ readv) {
    int b = blockIdx.x;
    int d4 = threadIdx.x;  // 128
    float4 s = make_float4(0.f, 0.f, 0.f, 0.f);
    #pragma unroll
    for (int c = 0; c < NSPLIT; c++) {
        float4 p = ((const float4*)g_rvpart)[((size_t)c * BS + b) * 128 + d4];
        s.x += p.x; s.y += p.y; s.z += p.z; s.w += p.w;
    }
    ((float4*)readv)[b * 128 + d4] = s;
}

// ---------------- launch ----------------------------------------------------
extern "C" void kernel_launch(void* const* d_in, const int* in_sizes, int n_in,
                              void* d_out, int out_size) {
    const float* h          = (const float*)d_in[0];
    const float* a          = (const float*)d_in[1];
    const float* prev_alpha = (const float*)d_in[3];
    const float* M          = (const float*)d_in[4];
    const float* Wv         = (const float*)d_in[5];
    const float* bv         = (const float*)d_in[6];
    const float* Wk1        = (const float*)d_in[7];
    const float* bk1        = (const float*)d_in[8];
    const float* Wk2        = (const float*)d_in[9];
    const float* bk2        = (const float*)d_in[10];
    const float* Wg1        = (const float*)d_in[11];
    const float* bg1        = (const float*)d_in[12];
    const float* Wg2        = (const float*)d_in[13];
    const float* bg2        = (const float*)d_in[14];

    float* out = (float*)d_out;
    float* out_readv = out + OUT_READV;
    float* out_other = out + OUT_OTHER;
    float* out_mnew  = out + OUT_MNEW;
    float* out_alpha = out + OUT_ALPHA;

    kernelnet_kernel<<<BS, 512>>>(a, Wk1, bk1, Wk2, bk2);
    gemm_kernel<<<dim3(32, 4), 256>>>(h, Wv, bv, Wg1, bg1, out_other);
    gate_kernel<<<32, dim3(32, 8)>>>(Wg2, bg2);
    conv_alpha_kernel<<<BS, 256>>>(prev_alpha, out_alpha);
    mupdate_kernel<<<dim3(NSPLIT, BS), 128>>>(M, out_alpha, out_mnew);
    rvreduce_kernel<<<BS, 128>>>(out_readv);
}

// round 3
// speedup vs baseline: 2.3283x; 1.0906x over previous
#include <cuda_runtime.h>
#include <math.h>

#define BS      256
#define HID     1024
#define ACT     16
#define MEM_DIM 512
#define NUM_MEM 1024
#define NSPLIT  16
#define NCHUNK  (NUM_MEM / NSPLIT)   // 64 memory rows per block

// Output layout (tuple concat): read_v | other_v | M_new | alpha
#define OUT_READV 0
#define OUT_OTHER (BS * MEM_DIM)                       // 131072
#define OUT_MNEW  (2 * BS * MEM_DIM)                   // 262144
#define OUT_ALPHA (2 * BS * MEM_DIM + BS * NUM_MEM * MEM_DIM)  // 134479872

// ---------------- scratch (device globals; no allocation allowed) ----------
__device__ __align__(16) float g_kern[BS * 9];
__device__ __align__(16) float g_G1[BS * MEM_DIM];
__device__ __align__(16) float g_gate[BS];
__device__ __align__(16) float g_erase[BS * MEM_DIM];
__device__ __align__(16) float g_add[BS * MEM_DIM];
__device__ __align__(16) float g_rvpart[NSPLIT * BS * MEM_DIM];  // 8 MB

__device__ __forceinline__ float leakyf(float x) { return x > 0.f ? x : 0.2f * x; }
__device__ __forceinline__ float sigmoidf_(float x) { return 1.f / (1.f + expf(-x)); }

// ---------------- kernel 1: kernel-net + flip + softmax --------------------
__global__ void kernelnet_kernel(const float* __restrict__ A,
                                 const float* __restrict__ Wk1,
                                 const float* __restrict__ bk1,
                                 const float* __restrict__ Wk2,
                                 const float* __restrict__ bk2) {
    int b = blockIdx.x;
    int tid = threadIdx.x;  // 512
    int lane = tid & 31, wid = tid >> 5;  // 16 warps
    __shared__ float sa[ACT], sna[ACT];
    __shared__ float spart[16][9], spartb[16][9];
    __shared__ float kk[9], kkb[9];
    __shared__ int sm_flag;

    if (tid < ACT) {
        float v = A[b * ACT + tid];
        sa[tid] = v;
        sna[tid] = v;
    }
    __syncthreads();
    if (tid == 0) {
        int am = 0;
        float best = sa[0];
        for (int i = 1; i < ACT; i++)
            if (sa[i] > best) { best = sa[i]; am = i; }
        int m = (am == 0);
        sm_flag = m;
        if (m) { sna[0] = 0.f; sna[1] = 1.f; }
    }
    __syncthreads();

    float x = bk1[tid], xb = x;
    #pragma unroll
    for (int i = 0; i < ACT; i++) {
        float w = Wk1[i * MEM_DIM + tid];
        x = fmaf(sa[i], w, x);
        xb = fmaf(sna[i], w, xb);
    }
    x = leakyf(x);
    xb = leakyf(xb);

    float p[9], pb[9];
    #pragma unroll
    for (int t = 0; t < 9; t++) {
        float w = Wk2[tid * 9 + t];
        p[t] = x * w;
        pb[t] = xb * w;
    }
    #pragma unroll
    for (int t = 0; t < 9; t++) {
        #pragma unroll
        for (int o = 16; o > 0; o >>= 1) {
            p[t] += __shfl_down_sync(0xffffffffu, p[t], o);
            pb[t] += __shfl_down_sync(0xffffffffu, pb[t], o);
        }
    }
    if (lane == 0) {
        #pragma unroll
        for (int t = 0; t < 9; t++) { spart[wid][t] = p[t]; spartb[wid][t] = pb[t]; }
    }
    __syncthreads();
    if (tid < 9) {
        float s = bk2[tid];
        #pragma unroll
        for (int w = 0; w < 16; w++) s += spart[w][tid];
        kk[tid] = s;
    } else if (tid >= 32 && tid < 41) {
        int t = tid - 32;
        float s = bk2[t];
        #pragma unroll
        for (int w = 0; w < 16; w++) s += spartb[w][t];
        kkb[t] = s;
    }
    __syncthreads();
    if (tid == 0) {
        float v[9];
        int m = sm_flag;
        #pragma unroll
        for (int i = 0; i < 9; i++) v[i] = m ? kkb[8 - i] : kk[i];
        float mx = v[0];
        #pragma unroll
        for (int i = 1; i < 9; i++) mx = fmaxf(mx, v[i]);
        float sum = 0.f;
        #pragma unroll
        for (int i = 0; i < 9; i++) { v[i] = expf(v[i] - mx); sum += v[i]; }
        float inv = 1.f / sum;
        #pragma unroll
        for (int i = 0; i < 9; i++) g_kern[b * 9 + i] = v[i] * inv;
    }
}

// ---------------- kernel 2: fused SGEMM slab h @ W -------------------------
// M=256, K=1024. BM=BN=64, BK=16, 256 thr, 4x4 micro-tile.
// n_off selects the global output column: [0,1536) Wv part, [1536,2048) Wg1.
__global__ void gemm_kernel(const float* __restrict__ H,
                            const float* __restrict__ Wv,
                            const float* __restrict__ bv,
                            const float* __restrict__ Wg1,
                            const float* __restrict__ bg1,
                            float* __restrict__ out_other,
                            int n_off) {
    const int n0 = n_off + blockIdx.x * 64;
    const int m0 = blockIdx.y * 64;
    const bool isG = (n0 >= 3 * MEM_DIM);
    const float* W = isG ? Wg1 : Wv;
    const int ldw = isG ? MEM_DIM : 3 * MEM_DIM;
    const int ncol0 = isG ? (n0 - 3 * MEM_DIM) : n0;

    __shared__ __align__(16) float As[16][64];
    __shared__ __align__(16) float Bs[16][64];

    int tid = threadIdx.x;
    int tx = tid & 15, ty = tid >> 4;
    int a_m = tid >> 2;
    int a_k = (tid & 3) * 4;
    int b_k = tid >> 4;
    int b_n = (tid & 15) * 4;

    float acc[4][4] = {};

    for (int k0 = 0; k0 < HID; k0 += 16) {
        float4 av = *(const float4*)(H + (size_t)(m0 + a_m) * HID + k0 + a_k);
        As[a_k + 0][a_m] = av.x;
        As[a_k + 1][a_m] = av.y;
        As[a_k + 2][a_m] = av.z;
        As[a_k + 3][a_m] = av.w;
        *(float4*)&Bs[b_k][b_n] =
            *(const float4*)(W + (size_t)(k0 + b_k) * ldw + ncol0 + b_n);
        __syncthreads();
        #pragma unroll
        for (int k = 0; k < 16; k++) {
            float4 a4 = *(const float4*)&As[k][ty * 4];
            float4 b4 = *(const float4*)&Bs[k][tx * 4];
            float ar[4] = {a4.x, a4.y, a4.z, a4.w};
            float br[4] = {b4.x, b4.y, b4.z, b4.w};
            #pragma unroll
            for (int i = 0; i < 4; i++)
                #pragma unroll
                for (int j = 0; j < 4; j++)
                    acc[i][j] = fmaf(ar[i], br[j], acc[i][j]);
        }
        __syncthreads();
    }

    #pragma unroll
    for (int i = 0; i < 4; i++) {
        int row = m0 + ty * 4 + i;
        #pragma unroll
        for (int j = 0; j < 4; j++) {
            int cc = ncol0 + tx * 4 + j;
            float val = acc[i][j];
            if (isG) {
                val += bg1[cc];
                g_G1[row * MEM_DIM + cc] = leakyf(val);
            } else {
                val += bv[cc];
                if (cc < MEM_DIM) {
                    g_erase[row * MEM_DIM + cc] = sigmoidf_(val);
                } else if (cc < 2 * MEM_DIM) {
                    g_add[row * MEM_DIM + (cc - MEM_DIM)] = val;
                } else {
                    out_other[row * MEM_DIM + (cc - 2 * MEM_DIM)] = val;
                }
            }
        }
    }
}

// ---------------- kernel 3: gate = sigmoid(G1 @ Wg2 + bg2) -----------------
__global__ void gate_kernel(const float* __restrict__ Wg2,
                            const float* __restrict__ bg2) {
    int b = blockIdx.x * 8 + threadIdx.y;
    float s = 0.f;
    for (int j = threadIdx.x; j < MEM_DIM; j += 32)
        s = fmaf(g_G1[b * MEM_DIM + j], Wg2[j], s);
    #pragma unroll
    for (int o = 16; o > 0; o >>= 1) s += __shfl_down_sync(0xffffffffu, s, o);
    if (threadIdx.x == 0) g_gate[b] = sigmoidf_(s + bg2[0]);
}

// ---------------- kernel 4: depthwise 3x3 conv + gated blend -> alpha ------
__global__ void conv_alpha_kernel(const float* __restrict__ prev_alpha,
                                  float* __restrict__ alpha_out) {
    int b = blockIdx.x;
    int tid = threadIdx.x;  // 256
    __shared__ float t[34][34];
    __shared__ float kk[9];
    float* tf = &t[0][0];
    for (int i = tid; i < 34 * 34; i += 256) tf[i] = 0.f;
    if (tid < 9) kk[tid] = g_kern[b * 9 + tid];
    __syncthreads();
    for (int i = tid; i < 1024; i += 256)
        t[1 + (i >> 5)][1 + (i & 31)] = prev_alpha[b * 1024 + i];
    __syncthreads();
    float g = g_gate[b];
    for (int i = tid; i < 1024; i += 256) {
        int y = i >> 5, x = i & 31;
        float s = 0.f;
        #pragma unroll
        for (int ky = 0; ky < 3; ky++)
            #pragma unroll
            for (int kx = 0; kx < 3; kx++)
                s = fmaf(t[y + ky][x + kx], kk[ky * 3 + kx], s);
        float pa = t[1 + y][1 + x];
        alpha_out[b * 1024 + i] = s * g + pa * (1.f - g);
    }
}

// ---------------- kernel 5: M update + partial read_v ----------------------
// grid (NSPLIT, BS), 128 threads; thread = one float4 of MEM_DIM, loops
// over NCHUNK=64 memory rows.
__global__ void mupdate_kernel(const float* __restrict__ M,
                               const float* __restrict__ alpha,
                               float* __restrict__ mnew) {
    int b = blockIdx.y;
    int c = blockIdx.x;          // n-chunk
    int d4 = threadIdx.x;        // 0..127
    __shared__ float sal[NCHUNK];
    if (d4 < NCHUNK) sal[d4] = alpha[b * NUM_MEM + c * NCHUNK + d4];
    __syncthreads();

    size_t base = (size_t)b * (NUM_MEM * 128) + (size_t)c * (NCHUNK * 128);
    const float4* Mb = (const float4*)M + base;
    float4* Ob = (float4*)mnew + base;
    float4 e = ((const float4*)g_erase)[b * 128 + d4];
    float4 v = ((const float4*)g_add)[b * 128 + d4];
    float4 rv = make_float4(0.f, 0.f, 0.f, 0.f);

    #pragma unroll 8
    for (int n = 0; n < NCHUNK; n++) {
        float a = sal[n];
        float4 m = __ldcs(&Mb[n * 128 + d4]);
        float4 mn;
        // M_new = M + a*(v - M*e)
        mn.x = fmaf(a, fmaf(-m.x, e.x, v.x), m.x);
        mn.y = fmaf(a, fmaf(-m.y, e.y, v.y), m.y);
        mn.z = fmaf(a, fmaf(-m.z, e.z, v.z), m.z);
        mn.w = fmaf(a, fmaf(-m.w, e.w, v.w), m.w);
        rv.x = fmaf(a, mn.x, rv.x);
        rv.y = fmaf(a, mn.y, rv.y);
        rv.z = fmaf(a, mn.z, rv.z);
        rv.w = fmaf(a, mn.w, rv.w);
        __stcs(&Ob[n * 128 + d4], mn);
    }
    ((float4*)g_rvpart)[((size_t)c * BS + b) * 128 + d4] = rv;
}

// ---------------- kernel 6: reduce read_v partials -------------------------
__global__ void rvreduce_kernel(float* __restrict__ readv) {
    int b = blockIdx.x;
    int d4 = threadIdx.x;  // 128
    float4 s = make_float4(0.f, 0.f, 0.f, 0.f);
    #pragma unroll
    for (int c = 0; c < NSPLIT; c++) {
        float4 p = ((const float4*)g_rvpart)[((size_t)c * BS + b) * 128 + d4];
        s.x += p.x; s.y += p.y; s.z += p.z; s.w += p.w;
    }
    ((float4*)readv)[b * 128 + d4] = s;
}

// ---------------- launch ----------------------------------------------------
extern "C" void kernel_launch(void* const* d_in, const int* in_sizes, int n_in,
                              void* d_out, int out_size) {
    const float* h          = (const float*)d_in[0];
    const float* a          = (const float*)d_in[1];
    const float* prev_alpha = (const float*)d_in[3];
    const float* M          = (const float*)d_in[4];
    const float* Wv         = (const float*)d_in[5];
    const float* bv         = (const float*)d_in[6];
    const float* Wk1        = (const float*)d_in[7];
    const float* bk1        = (const float*)d_in[8];
    const float* Wk2        = (const float*)d_in[9];
    const float* bk2        = (const float*)d_in[10];
    const float* Wg1        = (const float*)d_in[11];
    const float* bg1        = (const float*)d_in[12];
    const float* Wg2        = (const float*)d_in[13];
    const float* bg2        = (const float*)d_in[14];

    float* out = (float*)d_out;
    float* out_readv = out + OUT_READV;
    float* out_other = out + OUT_OTHER;
    float* out_mnew  = out + OUT_MNEW;
    float* out_alpha = out + OUT_ALPHA;

    // Lazy one-time creation of side stream + fork/join events (host-side
    // resources only; created on the eager correctness call, reused during
    // graph capture -> becomes proper graph edges). Work per call is
    // identical and deterministic.
    static cudaStream_t s1 = 0;
    static cudaEvent_t evFork = 0, evJoin = 0;
    static int tried = 0, ok = 0;
    if (!tried) {
        tried = 1;
        ok = (cudaStreamCreateWithFlags(&s1, cudaStreamNonBlocking) == cudaSuccess) &&
             (cudaEventCreateWithFlags(&evFork, cudaEventDisableTiming) == cudaSuccess) &&
             (cudaEventCreateWithFlags(&evJoin, cudaEventDisableTiming) == cudaSuccess);
    }

    if (ok) {
        // fork: Wv slab (24 column-blocks) on side stream
        cudaEventRecord(evFork, 0);
        cudaStreamWaitEvent(s1, evFork, 0);
        gemm_kernel<<<dim3(24, 4), 256, 0, s1>>>(h, Wv, bv, Wg1, bg1, out_other, 0);
        cudaEventRecord(evJoin, s1);

        // critical chain on default stream: Wg1 slab -> gate -> conv
        kernelnet_kernel<<<BS, 512>>>(a, Wk1, bk1, Wk2, bk2);
        gemm_kernel<<<dim3(8, 4), 256>>>(h, Wv, bv, Wg1, bg1, out_other, 1536);
        gate_kernel<<<32, dim3(32, 8)>>>(Wg2, bg2);
        conv_alpha_kernel<<<BS, 256>>>(prev_alpha, out_alpha);

        // join: mupdate needs erase/add (s1) + alpha (default)
        cudaStreamWaitEvent(0, evJoin, 0);
    } else {
        kernelnet_kernel<<<BS, 512>>>(a, Wk1, bk1, Wk2, bk2);
        gemm_kernel<<<dim3(24, 4), 256>>>(h, Wv, bv, Wg1, bg1, out_other, 0);
        gemm_kernel<<<dim3(8, 4), 256>>>(h, Wv, bv, Wg1, bg1, out_other, 1536);
        gate_kernel<<<32, dim3(32, 8)>>>(Wg2, bg2);
        conv_alpha_kernel<<<BS, 256>>>(prev_alpha, out_alpha);
    }

    mupdate_kernel<<<dim3(NSPLIT, BS), 128>>>(M, out_alpha, out_mnew);
    rvreduce_kernel<<<BS, 128>>>(out_readv);
}

// round 4
// speedup vs baseline: 2.4003x; 1.0309x over previous
#include <cuda_runtime.h>
#include <math.h>

#define BS      256
#define HID     1024
#define ACT     16
#define MEM_DIM 512
#define NUM_MEM 1024
#define NSPLIT  16
#define NCHUNK  (NUM_MEM / NSPLIT)   // 64 memory rows per block

// Output layout (tuple concat): read_v | other_v | M_new | alpha
#define OUT_READV 0
#define OUT_OTHER (BS * MEM_DIM)                       // 131072
#define OUT_MNEW  (2 * BS * MEM_DIM)                   // 262144
#define OUT_ALPHA (2 * BS * MEM_DIM + BS * NUM_MEM * MEM_DIM)  // 134479872

// ---------------- scratch (device globals; no allocation allowed) ----------
__device__ __align__(16) float g_kern[BS * 9];
__device__ __align__(16) float g_gatepart[8 * BS];   // per-colblock gate partials
__device__ __align__(16) float g_erase[BS * MEM_DIM];
__device__ __align__(16) float g_add[BS * MEM_DIM];
__device__ __align__(16) float g_rvpart[NSPLIT * BS * MEM_DIM];  // 8 MB

__device__ __forceinline__ float leakyf(float x) { return x > 0.f ? x : 0.2f * x; }
__device__ __forceinline__ float sigmoidf_(float x) { return 1.f / (1.f + expf(-x)); }

// ---------------- kernel 1: kernel-net + flip + softmax --------------------
__global__ void kernelnet_kernel(const float* __restrict__ A,
                                 const float* __restrict__ Wk1,
                                 const float* __restrict__ bk1,
                                 const float* __restrict__ Wk2,
                                 const float* __restrict__ bk2) {
    int b = blockIdx.x;
    int tid = threadIdx.x;  // 512
    int lane = tid & 31, wid = tid >> 5;  // 16 warps
    __shared__ float sa[ACT], sna[ACT];
    __shared__ float spart[16][9], spartb[16][9];
    __shared__ float kk[9], kkb[9];
    __shared__ int sm_flag;

    if (tid < ACT) {
        float v = A[b * ACT + tid];
        sa[tid] = v;
        sna[tid] = v;
    }
    __syncthreads();
    if (tid == 0) {
        int am = 0;
        float best = sa[0];
        for (int i = 1; i < ACT; i++)
            if (sa[i] > best) { best = sa[i]; am = i; }
        int m = (am == 0);
        sm_flag = m;
        if (m) { sna[0] = 0.f; sna[1] = 1.f; }
    }
    __syncthreads();

    float x = bk1[tid], xb = x;
    #pragma unroll
    for (int i = 0; i < ACT; i++) {
        float w = Wk1[i * MEM_DIM + tid];
        x = fmaf(sa[i], w, x);
        xb = fmaf(sna[i], w, xb);
    }
    x = leakyf(x);
    xb = leakyf(xb);

    float p[9], pb[9];
    #pragma unroll
    for (int t = 0; t < 9; t++) {
        float w = Wk2[tid * 9 + t];
        p[t] = x * w;
        pb[t] = xb * w;
    }
    #pragma unroll
    for (int t = 0; t < 9; t++) {
        #pragma unroll
        for (int o = 16; o > 0; o >>= 1) {
            p[t] += __shfl_down_sync(0xffffffffu, p[t], o);
            pb[t] += __shfl_down_sync(0xffffffffu, pb[t], o);
        }
    }
    if (lane == 0) {
        #pragma unroll
        for (int t = 0; t < 9; t++) { spart[wid][t] = p[t]; spartb[wid][t] = pb[t]; }
    }
    __syncthreads();
    if (tid < 9) {
        float s = bk2[tid];
        #pragma unroll
        for (int w = 0; w < 16; w++) s += spart[w][tid];
        kk[tid] = s;
    } else if (tid >= 32 && tid < 41) {
        int t = tid - 32;
        float s = bk2[t];
        #pragma unroll
        for (int w = 0; w < 16; w++) s += spartb[w][t];
        kkb[t] = s;
    }
    __syncthreads();
    if (tid == 0) {
        float v[9];
        int m = sm_flag;
        #pragma unroll
        for (int i = 0; i < 9; i++) v[i] = m ? kkb[8 - i] : kk[i];
        float mx = v[0];
        #pragma unroll
        for (int i = 1; i < 9; i++) mx = fmaxf(mx, v[i]);
        float sum = 0.f;
        #pragma unroll
        for (int i = 0; i < 9; i++) { v[i] = expf(v[i] - mx); sum += v[i]; }
        float inv = 1.f / sum;
        #pragma unroll
        for (int i = 0; i < 9; i++) g_kern[b * 9 + i] = v[i] * inv;
    }
}

// ---------------- kernel 2: fused SGEMM slab h @ W -------------------------
// M=256, K=1024. BM=BN=64, BK=16, 256 thr, 4x4 micro-tile.
// n_off selects global output column: [0,1536) Wv part, [1536,2048) Wg1.
// Wg1 blocks also emit per-colblock gate partials (fixed-order, deterministic).
__global__ void gemm_kernel(const float* __restrict__ H,
                            const float* __restrict__ Wv,
                            const float* __restrict__ bv,
                            const float* __restrict__ Wg1,
                            const float* __restrict__ bg1,
                            const float* __restrict__ Wg2,
                            float* __restrict__ out_other,
                            int n_off) {
    const int n0 = n_off + blockIdx.x * 64;
    const int m0 = blockIdx.y * 64;
    const bool isG = (n0 >= 3 * MEM_DIM);
    const float* W = isG ? Wg1 : Wv;
    const int ldw = isG ? MEM_DIM : 3 * MEM_DIM;
    const int ncol0 = isG ? (n0 - 3 * MEM_DIM) : n0;

    __shared__ __align__(16) float As[16][64];
    __shared__ __align__(16) float Bs[16][64];

    int tid = threadIdx.x;
    int tx = tid & 15, ty = tid >> 4;
    int a_m = tid >> 2;
    int a_k = (tid & 3) * 4;
    int b_k = tid >> 4;
    int b_n = (tid & 15) * 4;

    float acc[4][4] = {};

    for (int k0 = 0; k0 < HID; k0 += 16) {
        float4 av = *(const float4*)(H + (size_t)(m0 + a_m) * HID + k0 + a_k);
        As[a_k + 0][a_m] = av.x;
        As[a_k + 1][a_m] = av.y;
        As[a_k + 2][a_m] = av.z;
        As[a_k + 3][a_m] = av.w;
        *(float4*)&Bs[b_k][b_n] =
            *(const float4*)(W + (size_t)(k0 + b_k) * ldw + ncol0 + b_n);
        __syncthreads();
        #pragma unroll
        for (int k = 0; k < 16; k++) {
            float4 a4 = *(const float4*)&As[k][ty * 4];
            float4 b4 = *(const float4*)&Bs[k][tx * 4];
            float ar[4] = {a4.x, a4.y, a4.z, a4.w};
            float br[4] = {b4.x, b4.y, b4.z, b4.w};
            #pragma unroll
            for (int i = 0; i < 4; i++)
                #pragma unroll
                for (int j = 0; j < 4; j++)
                    acc[i][j] = fmaf(ar[i], br[j], acc[i][j]);
        }
        __syncthreads();
    }

    if (isG) {
        float gp[4] = {0.f, 0.f, 0.f, 0.f};
        #pragma unroll
        for (int i = 0; i < 4; i++) {
            int row = m0 + ty * 4 + i;
            #pragma unroll
            for (int j = 0; j < 4; j++) {
                int cc = ncol0 + tx * 4 + j;
                float val = leakyf(acc[i][j] + bg1[cc]);
                gp[i] = fmaf(val, Wg2[cc], gp[i]);
            }
        }
        // reduce across the 16 tx lanes (same ty parity group within warp)
        #pragma unroll
        for (int i = 0; i < 4; i++) {
            #pragma unroll
            for (int o = 8; o >= 1; o >>= 1)
                gp[i] += __shfl_xor_sync(0xffffffffu, gp[i], o);
        }
        if (tx == 0) {
            #pragma unroll
            for (int i = 0; i < 4; i++)
                g_gatepart[blockIdx.x * BS + m0 + ty * 4 + i] = gp[i];
        }
    } else {
        #pragma unroll
        for (int i = 0; i < 4; i++) {
            int row = m0 + ty * 4 + i;
            #pragma unroll
            for (int j = 0; j < 4; j++) {
                int cc = ncol0 + tx * 4 + j;
                float val = acc[i][j] + bv[cc];
                if (cc < MEM_DIM) {
                    g_erase[row * MEM_DIM + cc] = sigmoidf_(val);
                } else if (cc < 2 * MEM_DIM) {
                    g_add[row * MEM_DIM + (cc - MEM_DIM)] = val;
                } else {
                    out_other[row * MEM_DIM + (cc - 2 * MEM_DIM)] = val;
                }
            }
        }
    }
}

// ---------------- kernel 3: depthwise 3x3 conv + gated blend -> alpha ------
__global__ void conv_alpha_kernel(const float* __restrict__ prev_alpha,
                                  const float* __restrict__ bg2,
                                  float* __restrict__ alpha_out) {
    int b = blockIdx.x;
    int tid = threadIdx.x;  // 256
    __shared__ float t[34][34];
    __shared__ float kk[9];
    __shared__ float sgate;
    float* tf = &t[0][0];
    for (int i = tid; i < 34 * 34; i += 256) tf[i] = 0.f;
    if (tid < 9) kk[tid] = g_kern[b * 9 + tid];
    if (tid == 32) {
        float s = bg2[0];
        #pragma unroll
        for (int c = 0; c < 8; c++) s += g_gatepart[c * BS + b];
        sgate = sigmoidf_(s);
    }
    __syncthreads();
    for (int i = tid; i < 1024; i += 256)
        t[1 + (i >> 5)][1 + (i & 31)] = prev_alpha[b * 1024 + i];
    __syncthreads();
    float g = sgate;
    for (int i = tid; i < 1024; i += 256) {
        int y = i >> 5, x = i & 31;
        float s = 0.f;
        #pragma unroll
        for (int ky = 0; ky < 3; ky++)
            #pragma unroll
            for (int kx = 0; kx < 3; kx++)
                s = fmaf(t[y + ky][x + kx], kk[ky * 3 + kx], s);
        float pa = t[1 + y][1 + x];
        alpha_out[b * 1024 + i] = s * g + pa * (1.f - g);
    }
}

// ---------------- kernel 4: M update + partial read_v ----------------------
__global__ void mupdate_kernel(const float* __restrict__ M,
                               const float* __restrict__ alpha,
                               float* __restrict__ mnew) {
    int b = blockIdx.y;
    int c = blockIdx.x;          // n-chunk
    int d4 = threadIdx.x;        // 0..127
    __shared__ float sal[NCHUNK];
    if (d4 < NCHUNK) sal[d4] = alpha[b * NUM_MEM + c * NCHUNK + d4];
    __syncthreads();

    size_t base = (size_t)b * (NUM_MEM * 128) + (size_t)c * (NCHUNK * 128);
    const float4* Mb = (const float4*)M + base;
    float4* Ob = (float4*)mnew + base;
    float4 e = ((const float4*)g_erase)[b * 128 + d4];
    float4 v = ((const float4*)g_add)[b * 128 + d4];
    float4 rv = make_float4(0.f, 0.f, 0.f, 0.f);

    #pragma unroll 8
    for (int n = 0; n < NCHUNK; n++) {
        float a = sal[n];
        float4 m = __ldcs(&Mb[n * 128 + d4]);
        float4 mn;
        mn.x = fmaf(a, fmaf(-m.x, e.x, v.x), m.x);
        mn.y = fmaf(a, fmaf(-m.y, e.y, v.y), m.y);
        mn.z = fmaf(a, fmaf(-m.z, e.z, v.z), m.z);
        mn.w = fmaf(a, fmaf(-m.w, e.w, v.w), m.w);
        rv.x = fmaf(a, mn.x, rv.x);
        rv.y = fmaf(a, mn.y, rv.y);
        rv.z = fmaf(a, mn.z, rv.z);
        rv.w = fmaf(a, mn.w, rv.w);
        __stcs(&Ob[n * 128 + d4], mn);
    }
    ((float4*)g_rvpart)[((size_t)c * BS + b) * 128 + d4] = rv;
}

// ---------------- kernel 5: reduce read_v partials -------------------------
__global__ void rvreduce_kernel(float* __restrict__ readv) {
    int b = blockIdx.x;
    int d4 = threadIdx.x;  // 128
    float4 s = make_float4(0.f, 0.f, 0.f, 0.f);
    #pragma unroll
    for (int c = 0; c < NSPLIT; c++) {
        float4 p = ((const float4*)g_rvpart)[((size_t)c * BS + b) * 128 + d4];
        s.x += p.x; s.y += p.y; s.z += p.z; s.w += p.w;
    }
    ((float4*)readv)[b * 128 + d4] = s;
}

// ---------------- launch ----------------------------------------------------
extern "C" void kernel_launch(void* const* d_in, const int* in_sizes, int n_in,
                              void* d_out, int out_size) {
    const float* h          = (const float*)d_in[0];
    const float* a          = (const float*)d_in[1];
    const float* prev_alpha = (const float*)d_in[3];
    const float* M          = (const float*)d_in[4];
    const float* Wv         = (const float*)d_in[5];
    const float* bv         = (const float*)d_in[6];
    const float* Wk1        = (const float*)d_in[7];
    const float* bk1        = (const float*)d_in[8];
    const float* Wk2        = (const float*)d_in[9];
    const float* bk2        = (const float*)d_in[10];
    const float* Wg1        = (const float*)d_in[11];
    const float* bg1        = (const float*)d_in[12];
    const float* Wg2        = (const float*)d_in[13];
    const float* bg2        = (const float*)d_in[14];

    float* out = (float*)d_out;
    float* out_readv = out + OUT_READV;
    float* out_other = out + OUT_OTHER;
    float* out_mnew  = out + OUT_MNEW;
    float* out_alpha = out + OUT_ALPHA;

    static cudaStream_t s1 = 0;
    static cudaEvent_t evFork = 0, evJoin = 0, evJoin2 = 0;
    static int tried = 0, ok = 0;
    if (!tried) {
        tried = 1;
        ok = (cudaStreamCreateWithFlags(&s1, cudaStreamNonBlocking) == cudaSuccess) &&
             (cudaEventCreateWithFlags(&evFork, cudaEventDisableTiming) == cudaSuccess) &&
             (cudaEventCreateWithFlags(&evJoin, cudaEventDisableTiming) == cudaSuccess) &&
             (cudaEventCreateWithFlags(&evJoin2, cudaEventDisableTiming) == cudaSuccess);
    }

    if (ok) {
        // fork
        cudaEventRecord(evFork, 0);
        cudaStreamWaitEvent(s1, evFork, 0);
        // s1: erase+add slab (cols 0..1024) — needed before mupdate
        gemm_kernel<<<dim3(16, 4), 256, 0, s1>>>(h, Wv, bv, Wg1, bg1, Wg2, out_other, 0);
        cudaEventRecord(evJoin, s1);
        // s1: other_v slab (cols 1024..1536) — overlaps mupdate
        gemm_kernel<<<dim3(8, 4), 256, 0, s1>>>(h, Wv, bv, Wg1, bg1, Wg2, out_other, 1024);
        cudaEventRecord(evJoin2, s1);

        // default: kernelnet -> Wg1 gemm (+gate partials) -> conv
        kernelnet_kernel<<<BS, 512>>>(a, Wk1, bk1, Wk2, bk2);
        gemm_kernel<<<dim3(8, 4), 256>>>(h, Wv, bv, Wg1, bg1, Wg2, out_other, 1536);
        conv_alpha_kernel<<<BS, 256>>>(prev_alpha, bg2, out_alpha);

        cudaStreamWaitEvent(0, evJoin, 0);
        mupdate_kernel<<<dim3(NSPLIT, BS), 128>>>(M, out_alpha, out_mnew);
        rvreduce_kernel<<<BS, 128>>>(out_readv);
        // final join so capture sees all side-stream work joined
        cudaStreamWaitEvent(0, evJoin2, 0);
    } else {
        kernelnet_kernel<<<BS, 512>>>(a, Wk1, bk1, Wk2, bk2);
        gemm_kernel<<<dim3(16, 4), 256>>>(h, Wv, bv, Wg1, bg1, Wg2, out_other, 0);
        gemm_kernel<<<dim3(8, 4), 256>>>(h, Wv, bv, Wg1, bg1, Wg2, out_other, 1024);
        gemm_kernel<<<dim3(8, 4), 256>>>(h, Wv, bv, Wg1, bg1, Wg2, out_other, 1536);
        conv_alpha_kernel<<<BS, 256>>>(prev_alpha, bg2, out_alpha);
        mupdate_kernel<<<dim3(NSPLIT, BS), 128>>>(M, out_alpha, out_mnew);
        rvreduce_kernel<<<BS, 128>>>(out_readv);
    }
}

// round 5
// speedup vs baseline: 2.6828x; 1.1177x over previous
#include <cuda_runtime.h>
#include <math.h>

#define BS      256
#define HID     1024
#define ACT     16
#define MEM_DIM 512
#define NUM_MEM 1024
#define NSPLIT  16
#define NCHUNK  (NUM_MEM / NSPLIT)   // 64 memory rows per block

// GEMM split-K factors
#define KS_EA 2
#define KS_G1 4
#define KS_OT 2

// Output layout (tuple concat): read_v | other_v | M_new | alpha
#define OUT_READV 0
#define OUT_OTHER (BS * MEM_DIM)                       // 131072
#define OUT_MNEW  (2 * BS * MEM_DIM)                   // 262144
#define OUT_ALPHA (2 * BS * MEM_DIM + BS * NUM_MEM * MEM_DIM)  // 134479872

// ---------------- scratch (device globals; no allocation allowed) ----------
__device__ __align__(16) float g_kern[BS * 9];
__device__ __align__(16) float g_gate[BS];
__device__ __align__(16) float g_erase[BS * MEM_DIM];
__device__ __align__(16) float g_add[BS * MEM_DIM];
__device__ __align__(16) float g_rvpart[NSPLIT * BS * MEM_DIM];      // 8 MB
__device__ __align__(16) float g_part_ea[KS_EA * BS * 2 * MEM_DIM];  // 2 MB
__device__ __align__(16) float g_part_g1[KS_G1 * BS * MEM_DIM];      // 2 MB
__device__ __align__(16) float g_part_ot[KS_OT * BS * MEM_DIM];      // 1 MB

__device__ __forceinline__ float leakyf(float x) { return x > 0.f ? x : 0.2f * x; }
__device__ __forceinline__ float sigmoidf_(float x) { return 1.f / (1.f + expf(-x)); }

// ---------------- kernel 1: kernel-net + flip + softmax --------------------
__global__ void kernelnet_kernel(const float* __restrict__ A,
                                 const float* __restrict__ Wk1,
                                 const float* __restrict__ bk1,
                                 const float* __restrict__ Wk2,
                                 const float* __restrict__ bk2) {
    int b = blockIdx.x;
    int tid = threadIdx.x;  // 512
    int lane = tid & 31, wid = tid >> 5;  // 16 warps
    __shared__ float sa[ACT], sna[ACT];
    __shared__ float spart[16][9], spartb[16][9];
    __shared__ float kk[9], kkb[9];
    __shared__ int sm_flag;

    if (tid < ACT) {
        float v = A[b * ACT + tid];
        sa[tid] = v;
        sna[tid] = v;
    }
    __syncthreads();
    if (tid == 0) {
        int am = 0;
        float best = sa[0];
        for (int i = 1; i < ACT; i++)
            if (sa[i] > best) { best = sa[i]; am = i; }
        int m = (am == 0);
        sm_flag = m;
        if (m) { sna[0] = 0.f; sna[1] = 1.f; }
    }
    __syncthreads();

    float x = bk1[tid], xb = x;
    #pragma unroll
    for (int i = 0; i < ACT; i++) {
        float w = Wk1[i * MEM_DIM + tid];
        x = fmaf(sa[i], w, x);
        xb = fmaf(sna[i], w, xb);
    }
    x = leakyf(x);
    xb = leakyf(xb);

    float p[9], pb[9];
    #pragma unroll
    for (int t = 0; t < 9; t++) {
        float w = Wk2[tid * 9 + t];
        p[t] = x * w;
        pb[t] = xb * w;
    }
    #pragma unroll
    for (int t = 0; t < 9; t++) {
        #pragma unroll
        for (int o = 16; o > 0; o >>= 1) {
            p[t] += __shfl_down_sync(0xffffffffu, p[t], o);
            pb[t] += __shfl_down_sync(0xffffffffu, pb[t], o);
        }
    }
    if (lane == 0) {
        #pragma unroll
        for (int t = 0; t < 9; t++) { spart[wid][t] = p[t]; spartb[wid][t] = pb[t]; }
    }
    __syncthreads();
    if (tid < 9) {
        float s = bk2[tid];
        #pragma unroll
        for (int w = 0; w < 16; w++) s += spart[w][tid];
        kk[tid] = s;
    } else if (tid >= 32 && tid < 41) {
        int t = tid - 32;
        float s = bk2[t];
        #pragma unroll
        for (int w = 0; w < 16; w++) s += spartb[w][t];
        kkb[t] = s;
    }
    __syncthreads();
    if (tid == 0) {
        float v[9];
        int m = sm_flag;
        #pragma unroll
        for (int i = 0; i < 9; i++) v[i] = m ? kkb[8 - i] : kk[i];
        float mx = v[0];
        #pragma unroll
        for (int i = 1; i < 9; i++) mx = fmaxf(mx, v[i]);
        float sum = 0.f;
        #pragma unroll
        for (int i = 0; i < 9; i++) { v[i] = expf(v[i] - mx); sum += v[i]; }
        float inv = 1.f / sum;
        #pragma unroll
        for (int i = 0; i < 9; i++) g_kern[b * 9 + i] = v[i] * inv;
    }
}

// ---------------- kernel 2: split-K double-buffered SGEMM partials ---------
// C_part[kc] = H[:, kc*kper:(kc+1)*kper] @ W[kc*kper:..., wc0:wc0+ncols]
// BM=BN=64, BK=16, 256 threads, 4x4 micro-tile, 2-stage smem ping-pong.
__global__ void gemm_part_kernel(const float* __restrict__ H,
                                 const float* __restrict__ W, int ldw, int wc0,
                                 float* __restrict__ part, int ncols, int kper) {
    const int n0 = blockIdx.x * 64;
    const int m0 = blockIdx.y * 64;
    const int kbase = blockIdx.z * kper;

    __shared__ __align__(16) float As[2][16][64];
    __shared__ __align__(16) float Bs[2][16][64];

    int tid = threadIdx.x;
    int tx = tid & 15, ty = tid >> 4;
    int a_m = tid >> 2;
    int a_k = (tid & 3) * 4;
    int b_k = tid >> 4;
    int b_n = (tid & 15) * 4;

    const float* Aptr = H + (size_t)(m0 + a_m) * HID + kbase + a_k;
    const float* Bptr = W + (size_t)(kbase + b_k) * ldw + wc0 + n0 + b_n;

    float4 av = *(const float4*)Aptr;
    float4 bvv = *(const float4*)Bptr;
    As[0][a_k + 0][a_m] = av.x;
    As[0][a_k + 1][a_m] = av.y;
    As[0][a_k + 2][a_m] = av.z;
    As[0][a_k + 3][a_m] = av.w;
    *(float4*)&Bs[0][b_k][b_n] = bvv;
    __syncthreads();

    float acc[4][4] = {};
    int buf = 0;
    const int iters = kper / 16;

    for (int it = 1; it < iters; it++) {
        // prefetch next tile into registers (LDG overlaps compute below)
        av = *(const float4*)(Aptr + it * 16);
        bvv = *(const float4*)(Bptr + (size_t)it * 16 * ldw);

        #pragma unroll
        for (int k = 0; k < 16; k++) {
            float4 a4 = *(const float4*)&As[buf][k][ty * 4];
            float4 b4 = *(const float4*)&Bs[buf][k][tx * 4];
            float ar[4] = {a4.x, a4.y, a4.z, a4.w};
            float br[4] = {b4.x, b4.y, b4.z, b4.w};
            #pragma unroll
            for (int i = 0; i < 4; i++)
                #pragma unroll
                for (int j = 0; j < 4; j++)
                    acc[i][j] = fmaf(ar[i], br[j], acc[i][j]);
        }

        int nb = buf ^ 1;
        As[nb][a_k + 0][a_m] = av.x;
        As[nb][a_k + 1][a_m] = av.y;
        As[nb][a_k + 2][a_m] = av.z;
        As[nb][a_k + 3][a_m] = av.w;
        *(float4*)&Bs[nb][b_k][b_n] = bvv;
        __syncthreads();
        buf = nb;
    }

    #pragma unroll
    for (int k = 0; k < 16; k++) {
        float4 a4 = *(const float4*)&As[buf][k][ty * 4];
        float4 b4 = *(const float4*)&Bs[buf][k][tx * 4];
        float ar[4] = {a4.x, a4.y, a4.z, a4.w};
        float br[4] = {b4.x, b4.y, b4.z, b4.w};
        #pragma unroll
        for (int i = 0; i < 4; i++)
            #pragma unroll
            for (int j = 0; j < 4; j++)
                acc[i][j] = fmaf(ar[i], br[j], acc[i][j]);
    }

    #pragma unroll
    for (int i = 0; i < 4; i++) {
        float4 o = make_float4(acc[i][0], acc[i][1], acc[i][2], acc[i][3]);
        *(float4*)&part[((size_t)blockIdx.z * BS + m0 + ty * 4 + i) * ncols +
                        n0 + tx * 4] = o;
    }
}

// ---------------- epilogues -------------------------------------------------
// erase/add: cols 0..1024 of Wv output. 256 blocks x 256 thr, float4 each.
__global__ void epi_ea_kernel(const float* __restrict__ bv) {
    int idx = blockIdx.x * 256 + threadIdx.x;  // 65536 float4
    int row = idx >> 8;          // 256 float4 per row (1024 cols)
    int c = (idx & 255) * 4;
    float4 s = ((const float4*)g_part_ea)[(0 * BS + row) * 256 + (idx & 255)];
    #pragma unroll
    for (int ks = 1; ks < KS_EA; ks++) {
        float4 p = ((const float4*)g_part_ea)[((size_t)ks * BS + row) * 256 + (idx & 255)];
        s.x += p.x; s.y += p.y; s.z += p.z; s.w += p.w;
    }
    float4 b4 = *(const float4*)(bv + c);
    s.x += b4.x; s.y += b4.y; s.z += b4.z; s.w += b4.w;
    if (c < MEM_DIM) {
        s.x = sigmoidf_(s.x); s.y = sigmoidf_(s.y);
        s.z = sigmoidf_(s.z); s.w = sigmoidf_(s.w);
        *(float4*)&g_erase[row * MEM_DIM + c] = s;
    } else {
        *(float4*)&g_add[row * MEM_DIM + (c - MEM_DIM)] = s;
    }
}

// other_v: cols 1024..1536 of Wv output -> d_out. 128 blocks x 256 thr.
__global__ void epi_other_kernel(const float* __restrict__ bv,
                                 float* __restrict__ out_other) {
    int idx = blockIdx.x * 256 + threadIdx.x;  // 32768 float4
    int row = idx >> 7;          // 128 float4 per row (512 cols)
    int c = (idx & 127) * 4;
    float4 s = ((const float4*)g_part_ot)[(0 * BS + row) * 128 + (idx & 127)];
    #pragma unroll
    for (int ks = 1; ks < KS_OT; ks++) {
        float4 p = ((const float4*)g_part_ot)[((size_t)ks * BS + row) * 128 + (idx & 127)];
        s.x += p.x; s.y += p.y; s.z += p.z; s.w += p.w;
    }
    float4 b4 = *(const float4*)(bv + 2 * MEM_DIM + c);
    s.x += b4.x; s.y += b4.y; s.z += b4.z; s.w += b4.w;
    *(float4*)&out_other[row * MEM_DIM + c] = s;
}

// gate: per-row KS-sum + bias + leaky, dot Wg2, sigmoid. 256 blocks x 128 thr.
__global__ void epi_gate_kernel(const float* __restrict__ bg1,
                                const float* __restrict__ Wg2,
                                const float* __restrict__ bg2) {
    int b = blockIdx.x;
    int t = threadIdx.x;       // 128; each thread 4 contiguous cols
    int c = t * 4;
    __shared__ float wsum[4];
    float4 v = *(const float4*)(bg1 + c);
    #pragma unroll
    for (int ks = 0; ks < KS_G1; ks++) {
        float4 p = ((const float4*)g_part_g1)[((size_t)ks * BS + b) * 128 + t];
        v.x += p.x; v.y += p.y; v.z += p.z; v.w += p.w;
    }
    float4 w4 = *(const float4*)(Wg2 + c);
    float s = leakyf(v.x) * w4.x + leakyf(v.y) * w4.y +
              leakyf(v.z) * w4.z + leakyf(v.w) * w4.w;
    #pragma unroll
    for (int o = 16; o > 0; o >>= 1) s += __shfl_down_sync(0xffffffffu, s, o);
    if ((t & 31) == 0) wsum[t >> 5] = s;
    __syncthreads();
    if (t == 0)
        g_gate[b] = sigmoidf_(wsum[0] + wsum[1] + wsum[2] + wsum[3] + bg2[0]);
}

// ---------------- conv: depthwise 3x3 + gated blend -> alpha ---------------
__global__ void conv_alpha_kernel(const float* __restrict__ prev_alpha,
                                  float* __restrict__ alpha_out) {
    int b = blockIdx.x;
    int tid = threadIdx.x;  // 256
    __shared__ float t[34][34];
    __shared__ float kk[9];
    float* tf = &t[0][0];
    for (int i = tid; i < 34 * 34; i += 256) tf[i] = 0.f;
    if (tid < 9) kk[tid] = g_kern[b * 9 + tid];
    __syncthreads();
    for (int i = tid; i < 1024; i += 256)
        t[1 + (i >> 5)][1 + (i & 31)] = prev_alpha[b * 1024 + i];
    __syncthreads();
    float g = g_gate[b];
    for (int i = tid; i < 1024; i += 256) {
        int y = i >> 5, x = i & 31;
        float s = 0.f;
        #pragma unroll
        for (int ky = 0; ky < 3; ky++)
            #pragma unroll
            for (int kx = 0; kx < 3; kx++)
                s = fmaf(t[y + ky][x + kx], kk[ky * 3 + kx], s);
        float pa = t[1 + y][1 + x];
        alpha_out[b * 1024 + i] = s * g + pa * (1.f - g);
    }
}

// ---------------- M update + partial read_v --------------------------------
__global__ void mupdate_kernel(const float* __restrict__ M,
                               const float* __restrict__ alpha,
                               float* __restrict__ mnew) {
    int b = blockIdx.y;
    int c = blockIdx.x;
    int d4 = threadIdx.x;        // 0..127
    __shared__ float sal[NCHUNK];
    if (d4 < NCHUNK) sal[d4] = alpha[b * NUM_MEM + c * NCHUNK + d4];
    __syncthreads();

    size_t base = (size_t)b * (NUM_MEM * 128) + (size_t)c * (NCHUNK * 128);
    const float4* Mb = (const float4*)M + base;
    float4* Ob = (float4*)mnew + base;
    float4 e = ((const float4*)g_erase)[b * 128 + d4];
    float4 v = ((const float4*)g_add)[b * 128 + d4];
    float4 rv = make_float4(0.f, 0.f, 0.f, 0.f);

    #pragma unroll 8
    for (int n = 0; n < NCHUNK; n++) {
        float a = sal[n];
        float4 m = __ldcs(&Mb[n * 128 + d4]);
        float4 mn;
        mn.x = fmaf(a, fmaf(-m.x, e.x, v.x), m.x);
        mn.y = fmaf(a, fmaf(-m.y, e.y, v.y), m.y);
        mn.z = fmaf(a, fmaf(-m.z, e.z, v.z), m.z);
        mn.w = fmaf(a, fmaf(-m.w, e.w, v.w), m.w);
        rv.x = fmaf(a, mn.x, rv.x);
        rv.y = fmaf(a, mn.y, rv.y);
        rv.z = fmaf(a, mn.z, rv.z);
        rv.w = fmaf(a, mn.w, rv.w);
        __stcs(&Ob[n * 128 + d4], mn);
    }
    ((float4*)g_rvpart)[((size_t)c * BS + b) * 128 + d4] = rv;
}

// ---------------- reduce read_v partials -----------------------------------
__global__ void rvreduce_kernel(float* __restrict__ readv) {
    int b = blockIdx.x;
    int d4 = threadIdx.x;  // 128
    float4 s = make_float4(0.f, 0.f, 0.f, 0.f);
    #pragma unroll
    for (int c = 0; c < NSPLIT; c++) {
        float4 p = ((const float4*)g_rvpart)[((size_t)c * BS + b) * 128 + d4];
        s.x += p.x; s.y += p.y; s.z += p.z; s.w += p.w;
    }
    ((float4*)readv)[b * 128 + d4] = s;
}

// ---------------- launch ----------------------------------------------------
extern "C" void kernel_launch(void* const* d_in, const int* in_sizes, int n_in,
                              void* d_out, int out_size) {
    const float* h          = (const float*)d_in[0];
    const float* a          = (const float*)d_in[1];
    const float* prev_alpha = (const float*)d_in[3];
    const float* M          = (const float*)d_in[4];
    const float* Wv         = (const float*)d_in[5];
    const float* bv         = (const float*)d_in[6];
    const float* Wk1        = (const float*)d_in[7];
    const float* bk1        = (const float*)d_in[8];
    const float* Wk2        = (const float*)d_in[9];
    const float* bk2        = (const float*)d_in[10];
    const float* Wg1        = (const float*)d_in[11];
    const float* bg1        = (const float*)d_in[12];
    const float* Wg2        = (const float*)d_in[13];
    const float* bg2        = (const float*)d_in[14];

    float* out = (float*)d_out;
    float* out_readv = out + OUT_READV;
    float* out_other = out + OUT_OTHER;
    float* out_mnew  = out + OUT_MNEW;
    float* out_alpha = out + OUT_ALPHA;

    static cudaStream_t s1 = 0;
    static cudaEvent_t evFork = 0, evJoin = 0, evJoin2 = 0;
    static float *p_ea = 0, *p_g1 = 0, *p_ot = 0;
    static int tried = 0, ok = 0;
    if (!tried) {
        tried = 1;
        ok = (cudaStreamCreateWithFlags(&s1, cudaStreamNonBlocking) == cudaSuccess) &&
             (cudaEventCreateWithFlags(&evFork, cudaEventDisableTiming) == cudaSuccess) &&
             (cudaEventCreateWithFlags(&evJoin, cudaEventDisableTiming) == cudaSuccess) &&
             (cudaEventCreateWithFlags(&evJoin2, cudaEventDisableTiming) == cudaSuccess) &&
             (cudaGetSymbolAddress((void**)&p_ea, g_part_ea) == cudaSuccess) &&
             (cudaGetSymbolAddress((void**)&p_g1, g_part_g1) == cudaSuccess) &&
             (cudaGetSymbolAddress((void**)&p_ot, g_part_ot) == cudaSuccess);
    }
    if (!ok) return;  // cannot proceed without symbol addresses (never happens)

    // fork
    cudaEventRecord(evFork, 0);
    cudaStreamWaitEvent(s1, evFork, 0);

    // s1: erase/add slab (Wv cols 0..1024), KS=2 -> 128 blocks
    gemm_part_kernel<<<dim3(16, 4, KS_EA), 256, 0, s1>>>(
        h, Wv, 3 * MEM_DIM, 0, p_ea, 2 * MEM_DIM, HID / KS_EA);
    epi_ea_kernel<<<256, 256, 0, s1>>>(bv);
    cudaEventRecord(evJoin, s1);
    // s1: other_v slab (Wv cols 1024..1536), KS=2 -> 64 blocks (overlaps mupdate)
    gemm_part_kernel<<<dim3(8, 4, KS_OT), 256, 0, s1>>>(
        h, Wv, 3 * MEM_DIM, 2 * MEM_DIM, p_ot, MEM_DIM, HID / KS_OT);
    epi_other_kernel<<<128, 256, 0, s1>>>(bv, out_other);
    cudaEventRecord(evJoin2, s1);

    // default: kernelnet -> Wg1 gemm (KS=4, 128 blocks) -> gate -> conv
    kernelnet_kernel<<<BS, 512>>>(a, Wk1, bk1, Wk2, bk2);
    gemm_part_kernel<<<dim3(8, 4, KS_G1), 256>>>(
        h, Wg1, MEM_DIM, 0, p_g1, MEM_DIM, HID / KS_G1);
    epi_gate_kernel<<<BS, 128>>>(bg1, Wg2, bg2);
    conv_alpha_kernel<<<BS, 256>>>(prev_alpha, out_alpha);

    cudaStreamWaitEvent(0, evJoin, 0);
    mupdate_kernel<<<dim3(NSPLIT, BS), 128>>>(M, out_alpha, out_mnew);
    rvreduce_kernel<<<BS, 128>>>(out_readv);
    cudaStreamWaitEvent(0, evJoin2, 0);
}

// round 6
// speedup vs baseline: 2.7498x; 1.0250x over previous
#include <cuda_runtime.h>
#include <math.h>

#define BS      256
#define HID     1024
#define ACT     16
#define MEM_DIM 512
#define NUM_MEM 1024
#define NSPLIT  16
#define NCHUNK  (NUM_MEM / NSPLIT)   // 64 memory rows per block

// GEMM split-K factors
#define KS_EA 2
#define KS_G1 4
#define KS_OT 2

// Output layout (tuple concat): read_v | other_v | M_new | alpha
#define OUT_READV 0
#define OUT_OTHER (BS * MEM_DIM)                       // 131072
#define OUT_MNEW  (2 * BS * MEM_DIM)                   // 262144
#define OUT_ALPHA (2 * BS * MEM_DIM + BS * NUM_MEM * MEM_DIM)  // 134479872

// ---------------- scratch (device globals; no allocation allowed) ----------
__device__ __align__(16) float g_rvpart[NSPLIT * BS * MEM_DIM];      // 8 MB
__device__ __align__(16) float g_part_ea[KS_EA * BS * 2 * MEM_DIM];  // 2 MB
__device__ __align__(16) float g_part_g1[KS_G1 * BS * MEM_DIM];      // 2 MB
__device__ __align__(16) float g_part_ot[KS_OT * BS * MEM_DIM];      // 1 MB

__device__ __forceinline__ float leakyf(float x) { return x > 0.f ? x : 0.2f * x; }
__device__ __forceinline__ float sigmoidf_(float x) { return 1.f / (1.f + expf(-x)); }

// ---------------- split-K double-buffered SGEMM partials -------------------
// C_part[kc] = H[:, kc*kper:(kc+1)*kper] @ W[kc*kper:..., wc0:wc0+ncols]
// BM=BN=64, BK=16, 256 threads, 4x4 micro-tile, 2-stage smem ping-pong.
__global__ void gemm_part_kernel(const float* __restrict__ H,
                                 const float* __restrict__ W, int ldw, int wc0,
                                 float* __restrict__ part, int ncols, int kper) {
    const int n0 = blockIdx.x * 64;
    const int m0 = blockIdx.y * 64;
    const int kbase = blockIdx.z * kper;

    __shared__ __align__(16) float As[2][16][64];
    __shared__ __align__(16) float Bs[2][16][64];

    int tid = threadIdx.x;
    int tx = tid & 15, ty = tid >> 4;
    int a_m = tid >> 2;
    int a_k = (tid & 3) * 4;
    int b_k = tid >> 4;
    int b_n = (tid & 15) * 4;

    const float* Aptr = H + (size_t)(m0 + a_m) * HID + kbase + a_k;
    const float* Bptr = W + (size_t)(kbase + b_k) * ldw + wc0 + n0 + b_n;

    float4 av = *(const float4*)Aptr;
    float4 bvv = *(const float4*)Bptr;
    As[0][a_k + 0][a_m] = av.x;
    As[0][a_k + 1][a_m] = av.y;
    As[0][a_k + 2][a_m] = av.z;
    As[0][a_k + 3][a_m] = av.w;
    *(float4*)&Bs[0][b_k][b_n] = bvv;
    __syncthreads();

    float acc[4][4] = {};
    int buf = 0;
    const int iters = kper / 16;

    for (int it = 1; it < iters; it++) {
        av = *(const float4*)(Aptr + it * 16);
        bvv = *(const float4*)(Bptr + (size_t)it * 16 * ldw);

        #pragma unroll
        for (int k = 0; k < 16; k++) {
            float4 a4 = *(const float4*)&As[buf][k][ty * 4];
            float4 b4 = *(const float4*)&Bs[buf][k][tx * 4];
            float ar[4] = {a4.x, a4.y, a4.z, a4.w};
            float br[4] = {b4.x, b4.y, b4.z, b4.w};
            #pragma unroll
            for (int i = 0; i < 4; i++)
                #pragma unroll
                for (int j = 0; j < 4; j++)
                    acc[i][j] = fmaf(ar[i], br[j], acc[i][j]);
        }

        int nb = buf ^ 1;
        As[nb][a_k + 0][a_m] = av.x;
        As[nb][a_k + 1][a_m] = av.y;
        As[nb][a_k + 2][a_m] = av.z;
        As[nb][a_k + 3][a_m] = av.w;
        *(float4*)&Bs[nb][b_k][b_n] = bvv;
        __syncthreads();
        buf = nb;
    }

    #pragma unroll
    for (int k = 0; k < 16; k++) {
        float4 a4 = *(const float4*)&As[buf][k][ty * 4];
        float4 b4 = *(const float4*)&Bs[buf][k][tx * 4];
        float ar[4] = {a4.x, a4.y, a4.z, a4.w};
        float br[4] = {b4.x, b4.y, b4.z, b4.w};
        #pragma unroll
        for (int i = 0; i < 4; i++)
            #pragma unroll
            for (int j = 0; j < 4; j++)
                acc[i][j] = fmaf(ar[i], br[j], acc[i][j]);
    }

    #pragma unroll
    for (int i = 0; i < 4; i++) {
        float4 o = make_float4(acc[i][0], acc[i][1], acc[i][2], acc[i][3]);
        *(float4*)&part[((size_t)blockIdx.z * BS + m0 + ty * 4 + i) * ncols +
                        n0 + tx * 4] = o;
    }
}

// ---------------- epilogue: other_v -> d_out -------------------------------
__global__ void epi_other_kernel(const float* __restrict__ bv,
                                 float* __restrict__ out_other) {
    int idx = blockIdx.x * 256 + threadIdx.x;  // 32768 float4
    int row = idx >> 7;
    int c = (idx & 127) * 4;
    float4 s = ((const float4*)g_part_ot)[(0 * BS + row) * 128 + (idx & 127)];
    #pragma unroll
    for (int ks = 1; ks < KS_OT; ks++) {
        float4 p = ((const float4*)g_part_ot)[((size_t)ks * BS + row) * 128 + (idx & 127)];
        s.x += p.x; s.y += p.y; s.z += p.z; s.w += p.w;
    }
    float4 b4 = *(const float4*)(bv + 2 * MEM_DIM + c);
    s.x += b4.x; s.y += b4.y; s.z += b4.z; s.w += b4.w;
    *(float4*)&out_other[row * MEM_DIM + c] = s;
}

// ---------------- fused: kernel-net + gate + 3x3 conv + blend -> alpha -----
// one block per batch row, 256 threads.
__global__ void conv_fused_kernel(const float* __restrict__ A,
                                  const float* __restrict__ Wk1,
                                  const float* __restrict__ bk1,
                                  const float* __restrict__ Wk2,
                                  const float* __restrict__ bk2,
                                  const float* __restrict__ bg1,
                                  const float* __restrict__ Wg2,
                                  const float* __restrict__ bg2,
                                  const float* __restrict__ prev_alpha,
                                  float* __restrict__ alpha_out) {
    int b = blockIdx.x;
    int tid = threadIdx.x;  // 256
    int lane = tid & 31, wid = tid >> 5;  // 8 warps

    __shared__ float sa[ACT], sna[ACT];
    __shared__ float spart[8][9], spartb[8][9], sgp[8];
    __shared__ float kk[9];
    __shared__ float sgate;
    __shared__ int sm_flag;
    __shared__ float t[34][34];

    // ---- load action vector, argmax flip ----
    if (tid < ACT) {
        float v = A[b * ACT + tid];
        sa[tid] = v;
        sna[tid] = v;
    }
    __syncthreads();
    if (tid == 0) {
        int am = 0;
        float best = sa[0];
        for (int i = 1; i < ACT; i++)
            if (sa[i] > best) { best = sa[i]; am = i; }
        int m = (am == 0);
        sm_flag = m;
        if (m) { sna[0] = 0.f; sna[1] = 1.f; }
    }
    // start zeroing the halo tile while waiting
    {
        float* tf = &t[0][0];
        for (int i = tid; i < 34 * 34; i += 256) tf[i] = 0.f;
    }
    __syncthreads();

    // ---- kernel-net (2 hidden units per thread) + gate partial ----
    float p[9] = {}, pb[9] = {};
    #pragma unroll
    for (int half = 0; half < 2; half++) {
        int j = tid + half * 256;
        float x = bk1[j], xb = x;
        #pragma unroll
        for (int i = 0; i < ACT; i++) {
            float w = Wk1[i * MEM_DIM + j];
            x = fmaf(sa[i], w, x);
            xb = fmaf(sna[i], w, xb);
        }
        x = leakyf(x);
        xb = leakyf(xb);
        #pragma unroll
        for (int tt = 0; tt < 9; tt++) {
            float w = Wk2[j * 9 + tt];
            p[tt] = fmaf(x, w, p[tt]);
            pb[tt] = fmaf(xb, w, pb[tt]);
        }
    }
    // gate partial: cols tid and tid+256
    float gv = 0.f;
    #pragma unroll
    for (int half = 0; half < 2; half++) {
        int c = tid + half * 256;
        float v = bg1[c];
        #pragma unroll
        for (int ks = 0; ks < KS_G1; ks++)
            v += g_part_g1[((size_t)ks * BS + b) * MEM_DIM + c];
        gv = fmaf(leakyf(v), Wg2[c], gv);
    }

    // warp reductions
    #pragma unroll
    for (int tt = 0; tt < 9; tt++) {
        #pragma unroll
        for (int o = 16; o > 0; o >>= 1) {
            p[tt] += __shfl_down_sync(0xffffffffu, p[tt], o);
            pb[tt] += __shfl_down_sync(0xffffffffu, pb[tt], o);
        }
    }
    #pragma unroll
    for (int o = 16; o > 0; o >>= 1) gv += __shfl_down_sync(0xffffffffu, gv, o);
    if (lane == 0) {
        #pragma unroll
        for (int tt = 0; tt < 9; tt++) { spart[wid][tt] = p[tt]; spartb[wid][tt] = pb[tt]; }
        sgp[wid] = gv;
    }
    __syncthreads();

    if (tid == 64) {
        float s = bg2[0];
        #pragma unroll
        for (int w = 0; w < 8; w++) s += sgp[w];
        sgate = sigmoidf_(s);
    }
    if (tid == 0) {
        float kkr[9], kkbr[9];
        #pragma unroll
        for (int tt = 0; tt < 9; tt++) {
            float s = bk2[tt], sb = bk2[tt];
            #pragma unroll
            for (int w = 0; w < 8; w++) { s += spart[w][tt]; sb += spartb[w][tt]; }
            kkr[tt] = s; kkbr[tt] = sb;
        }
        int m = sm_flag;
        float v[9];
        #pragma unroll
        for (int i = 0; i < 9; i++) v[i] = m ? kkbr[8 - i] : kkr[i];
        float mx = v[0];
        #pragma unroll
        for (int i = 1; i < 9; i++) mx = fmaxf(mx, v[i]);
        float sum = 0.f;
        #pragma unroll
        for (int i = 0; i < 9; i++) { v[i] = expf(v[i] - mx); sum += v[i]; }
        float inv = 1.f / sum;
        #pragma unroll
        for (int i = 0; i < 9; i++) kk[i] = v[i] * inv;
    }
    __syncthreads();

    // ---- load prev_alpha tile, conv, blend ----
    for (int i = tid; i < 1024; i += 256)
        t[1 + (i >> 5)][1 + (i & 31)] = prev_alpha[b * 1024 + i];
    __syncthreads();
    float g = sgate;
    for (int i = tid; i < 1024; i += 256) {
        int y = i >> 5, x = i & 31;
        float s = 0.f;
        #pragma unroll
        for (int ky = 0; ky < 3; ky++)
            #pragma unroll
            for (int kx = 0; kx < 3; kx++)
                s = fmaf(t[y + ky][x + kx], kk[ky * 3 + kx], s);
        float pa = t[1 + y][1 + x];
        alpha_out[b * 1024 + i] = s * g + pa * (1.f - g);
    }
}

// ---------------- M update (inline erase/add epilogue) + partial read_v ----
__global__ void mupdate_kernel(const float* __restrict__ M,
                               const float* __restrict__ alpha,
                               const float* __restrict__ bv,
                               float* __restrict__ mnew) {
    int b = blockIdx.y;
    int c = blockIdx.x;
    int d4 = threadIdx.x;        // 0..127
    __shared__ float sal[NCHUNK];
    if (d4 < NCHUNK) sal[d4] = alpha[b * NUM_MEM + c * NCHUNK + d4];

    // reconstruct erase/add for (b, d4) from KS partials (+bias)
    float4 e = *(const float4*)(bv + d4 * 4);
    float4 v = *(const float4*)(bv + MEM_DIM + d4 * 4);
    #pragma unroll
    for (int ks = 0; ks < KS_EA; ks++) {
        float4 pe = ((const float4*)g_part_ea)[((size_t)ks * BS + b) * 256 + d4];
        float4 pv = ((const float4*)g_part_ea)[((size_t)ks * BS + b) * 256 + 128 + d4];
        e.x += pe.x; e.y += pe.y; e.z += pe.z; e.w += pe.w;
        v.x += pv.x; v.y += pv.y; v.z += pv.z; v.w += pv.w;
    }
    e.x = sigmoidf_(e.x); e.y = sigmoidf_(e.y);
    e.z = sigmoidf_(e.z); e.w = sigmoidf_(e.w);
    __syncthreads();

    size_t base = (size_t)b * (NUM_MEM * 128) + (size_t)c * (NCHUNK * 128);
    const float4* Mb = (const float4*)M + base;
    float4* Ob = (float4*)mnew + base;
    float4 rv = make_float4(0.f, 0.f, 0.f, 0.f);

    #pragma unroll 8
    for (int n = 0; n < NCHUNK; n++) {
        float a = sal[n];
        float4 m = __ldcs(&Mb[n * 128 + d4]);
        float4 mn;
        mn.x = fmaf(a, fmaf(-m.x, e.x, v.x), m.x);
        mn.y = fmaf(a, fmaf(-m.y, e.y, v.y), m.y);
        mn.z = fmaf(a, fmaf(-m.z, e.z, v.z), m.z);
        mn.w = fmaf(a, fmaf(-m.w, e.w, v.w), m.w);
        rv.x = fmaf(a, mn.x, rv.x);
        rv.y = fmaf(a, mn.y, rv.y);
        rv.z = fmaf(a, mn.z, rv.z);
        rv.w = fmaf(a, mn.w, rv.w);
        __stcs(&Ob[n * 128 + d4], mn);
    }
    ((float4*)g_rvpart)[((size_t)c * BS + b) * 128 + d4] = rv;
}

// ---------------- reduce read_v partials -----------------------------------
__global__ void rvreduce_kernel(float* __restrict__ readv) {
    int b = blockIdx.x;
    int d4 = threadIdx.x;  // 128
    float4 s = make_float4(0.f, 0.f, 0.f, 0.f);
    #pragma unroll
    for (int c = 0; c < NSPLIT; c++) {
        float4 p = ((const float4*)g_rvpart)[((size_t)c * BS + b) * 128 + d4];
        s.x += p.x; s.y += p.y; s.z += p.z; s.w += p.w;
    }
    ((float4*)readv)[b * 128 + d4] = s;
}

// ---------------- launch ----------------------------------------------------
extern "C" void kernel_launch(void* const* d_in, const int* in_sizes, int n_in,
                              void* d_out, int out_size) {
    const float* h          = (const float*)d_in[0];
    const float* a          = (const float*)d_in[1];
    const float* prev_alpha = (const float*)d_in[3];
    const float* M          = (const float*)d_in[4];
    const float* Wv         = (const float*)d_in[5];
    const float* bv         = (const float*)d_in[6];
    const float* Wk1        = (const float*)d_in[7];
    const float* bk1        = (const float*)d_in[8];
    const float* Wk2        = (const float*)d_in[9];
    const float* bk2        = (const float*)d_in[10];
    const float* Wg1        = (const float*)d_in[11];
    const float* bg1        = (const float*)d_in[12];
    const float* Wg2        = (const float*)d_in[13];
    const float* bg2        = (const float*)d_in[14];

    float* out = (float*)d_out;
    float* out_readv = out + OUT_READV;
    float* out_other = out + OUT_OTHER;
    float* out_mnew  = out + OUT_MNEW;
    float* out_alpha = out + OUT_ALPHA;

    static cudaStream_t s1 = 0;
    static cudaEvent_t evFork = 0, evJoin = 0, evJoin2 = 0;
    static float *p_ea = 0, *p_g1 = 0, *p_ot = 0;
    static int tried = 0, ok = 0;
    if (!tried) {
        tried = 1;
        ok = (cudaStreamCreateWithFlags(&s1, cudaStreamNonBlocking) == cudaSuccess) &&
             (cudaEventCreateWithFlags(&evFork, cudaEventDisableTiming) == cudaSuccess) &&
             (cudaEventCreateWithFlags(&evJoin, cudaEventDisableTiming) == cudaSuccess) &&
             (cudaEventCreateWithFlags(&evJoin2, cudaEventDisableTiming) == cudaSuccess) &&
             (cudaGetSymbolAddress((void**)&p_ea, g_part_ea) == cudaSuccess) &&
             (cudaGetSymbolAddress((void**)&p_g1, g_part_g1) == cudaSuccess) &&
             (cudaGetSymbolAddress((void**)&p_ot, g_part_ot) == cudaSuccess);
    }
    if (!ok) return;

    // fork
    cudaEventRecord(evFork, 0);
    cudaStreamWaitEvent(s1, evFork, 0);

    // s1: erase/add slab partials (Wv cols 0..1024), KS=2 -> 128 blocks
    gemm_part_kernel<<<dim3(16, 4, KS_EA), 256, 0, s1>>>(
        h, Wv, 3 * MEM_DIM, 0, p_ea, 2 * MEM_DIM, HID / KS_EA);
    cudaEventRecord(evJoin, s1);
    // s1: other_v slab (overlaps conv/mupdate)
    gemm_part_kernel<<<dim3(8, 4, KS_OT), 256, 0, s1>>>(
        h, Wv, 3 * MEM_DIM, 2 * MEM_DIM, p_ot, MEM_DIM, HID / KS_OT);
    epi_other_kernel<<<128, 256, 0, s1>>>(bv, out_other);
    cudaEventRecord(evJoin2, s1);

    // default: g1 gemm partials -> fused kernelnet+gate+conv -> mupdate chain
    gemm_part_kernel<<<dim3(8, 4, KS_G1), 256>>>(
        h, Wg1, MEM_DIM, 0, p_g1, MEM_DIM, HID / KS_G1);
    conv_fused_kernel<<<BS, 256>>>(a, Wk1, bk1, Wk2, bk2, bg1, Wg2, bg2,
                                   prev_alpha, out_alpha);

    cudaStreamWaitEvent(0, evJoin, 0);
    mupdate_kernel<<<dim3(NSPLIT, BS), 128>>>(M, out_alpha, bv, out_mnew);
    rvreduce_kernel<<<BS, 128>>>(out_readv);
    cudaStreamWaitEvent(0, evJoin2, 0);
}

// round 8
// speedup vs baseline: 3.0308x; 1.1022x over previous
#include <cuda_runtime.h>
#include <math.h>

#define BS      256
#define HID     1024
#define ACT     16
#define MEM_DIM 512
#define NUM_MEM 1024
#define NSPLIT  32
#define NCHUNK  (NUM_MEM / NSPLIT)   // 32 memory rows per block
#define MBATCH  8

// GEMM split-K factors
#define KS_EA 2
#define KS_G1 4
#define KS_OT 2

// Output layout (tuple concat): read_v | other_v | M_new | alpha
#define OUT_READV 0
#define OUT_OTHER (BS * MEM_DIM)                       // 131072
#define OUT_MNEW  (2 * BS * MEM_DIM)                   // 262144
#define OUT_ALPHA (2 * BS * MEM_DIM + BS * NUM_MEM * MEM_DIM)  // 134479872

// ---------------- scratch (device globals; no allocation allowed) ----------
__device__ __align__(16) float g_rvpart[NSPLIT * BS * MEM_DIM];      // 16 MB
__device__ __align__(16) float g_part_ea[KS_EA * BS * 2 * MEM_DIM];  // 2 MB
__device__ __align__(16) float g_part_g1[KS_G1 * BS * MEM_DIM];      // 2 MB
__device__ __align__(16) float g_part_ot[KS_OT * BS * MEM_DIM];      // 1 MB

__device__ __forceinline__ float leakyf(float x) { return x > 0.f ? x : 0.2f * x; }
__device__ __forceinline__ float sigmoidf_(float x) { return 1.f / (1.f + expf(-x)); }

// ---------------- split-K double-buffered SGEMM partials -------------------
__global__ void gemm_part_kernel(const float* __restrict__ H,
                                 const float* __restrict__ W, int ldw, int wc0,
                                 float* __restrict__ part, int ncols, int kper) {
    const int n0 = blockIdx.x * 64;
    const int m0 = blockIdx.y * 64;
    const int kbase = blockIdx.z * kper;

    __shared__ __align__(16) float As[2][16][64];
    __shared__ __align__(16) float Bs[2][16][64];

    int tid = threadIdx.x;
    int tx = tid & 15, ty = tid >> 4;
    int a_m = tid >> 2;
    int a_k = (tid & 3) * 4;
    int b_k = tid >> 4;
    int b_n = (tid & 15) * 4;

    const float* Aptr = H + (size_t)(m0 + a_m) * HID + kbase + a_k;
    const float* Bptr = W + (size_t)(kbase + b_k) * ldw + wc0 + n0 + b_n;

    float4 av = *(const float4*)Aptr;
    float4 bvv = *(const float4*)Bptr;
    As[0][a_k + 0][a_m] = av.x;
    As[0][a_k + 1][a_m] = av.y;
    As[0][a_k + 2][a_m] = av.z;
    As[0][a_k + 3][a_m] = av.w;
    *(float4*)&Bs[0][b_k][b_n] = bvv;
    __syncthreads();

    float acc[4][4] = {};
    int buf = 0;
    const int iters = kper / 16;

    for (int it = 1; it < iters; it++) {
        av = *(const float4*)(Aptr + it * 16);
        bvv = *(const float4*)(Bptr + (size_t)it * 16 * ldw);

        #pragma unroll
        for (int k = 0; k < 16; k++) {
            float4 a4 = *(const float4*)&As[buf][k][ty * 4];
            float4 b4 = *(const float4*)&Bs[buf][k][tx * 4];
            float ar[4] = {a4.x, a4.y, a4.z, a4.w};
            float br[4] = {b4.x, b4.y, b4.z, b4.w};
            #pragma unroll
            for (int i = 0; i < 4; i++)
                #pragma unroll
                for (int j = 0; j < 4; j++)
                    acc[i][j] = fmaf(ar[i], br[j], acc[i][j]);
        }

        int nb = buf ^ 1;
        As[nb][a_k + 0][a_m] = av.x;
        As[nb][a_k + 1][a_m] = av.y;
        As[nb][a_k + 2][a_m] = av.z;
        As[nb][a_k + 3][a_m] = av.w;
        *(float4*)&Bs[nb][b_k][b_n] = bvv;
        __syncthreads();
        buf = nb;
    }

    #pragma unroll
    for (int k = 0; k < 16; k++) {
        float4 a4 = *(const float4*)&As[buf][k][ty * 4];
        float4 b4 = *(const float4*)&Bs[buf][k][tx * 4];
        float ar[4] = {a4.x, a4.y, a4.z, a4.w};
        float br[4] = {b4.x, b4.y, b4.z, b4.w};
        #pragma unroll
        for (int i = 0; i < 4; i++)
            #pragma unroll
            for (int j = 0; j < 4; j++)
                acc[i][j] = fmaf(ar[i], br[j], acc[i][j]);
    }

    #pragma unroll
    for (int i = 0; i < 4; i++) {
        float4 o = make_float4(acc[i][0], acc[i][1], acc[i][2], acc[i][3]);
        *(float4*)&part[((size_t)blockIdx.z * BS + m0 + ty * 4 + i) * ncols +
                        n0 + tx * 4] = o;
    }
}

// ---------------- epilogue: other_v -> d_out -------------------------------
__global__ void epi_other_kernel(const float* __restrict__ bv,
                                 float* __restrict__ out_other) {
    int idx = blockIdx.x * 256 + threadIdx.x;  // 32768 float4
    int row = idx >> 7;
    int c = (idx & 127) * 4;
    float4 s = ((const float4*)g_part_ot)[(0 * BS + row) * 128 + (idx & 127)];
    #pragma unroll
    for (int ks = 1; ks < KS_OT; ks++) {
        float4 p = ((const float4*)g_part_ot)[((size_t)ks * BS + row) * 128 + (idx & 127)];
        s.x += p.x; s.y += p.y; s.z += p.z; s.w += p.w;
    }
    float4 b4 = *(const float4*)(bv + 2 * MEM_DIM + c);
    s.x += b4.x; s.y += b4.y; s.z += b4.z; s.w += b4.w;
    *(float4*)&out_other[row * MEM_DIM + c] = s;
}

// ---------------- fused: kernel-net + gate + 3x3 conv + blend -> alpha -----
__global__ void conv_fused_kernel(const float* __restrict__ A,
                                  const float* __restrict__ Wk1,
                                  const float* __restrict__ bk1,
                                  const float* __restrict__ Wk2,
                                  const float* __restrict__ bk2,
                                  const float* __restrict__ bg1,
                                  const float* __restrict__ Wg2,
                                  const float* __restrict__ bg2,
                                  const float* __restrict__ prev_alpha,
                                  float* __restrict__ alpha_out) {
    int b = blockIdx.x;
    int tid = threadIdx.x;  // 256
    int lane = tid & 31, wid = tid >> 5;  // 8 warps

    __shared__ float sa[ACT], sna[ACT];
    __shared__ float spart[8][9], spartb[8][9], sgp[8];
    __shared__ float kk[9];
    __shared__ float sgate;
    __shared__ int sm_flag;
    __shared__ float t[34][34];

    if (tid < ACT) {
        float v = A[b * ACT + tid];
        sa[tid] = v;
        sna[tid] = v;
    }
    __syncthreads();
    if (tid == 0) {
        int am = 0;
        float best = sa[0];
        for (int i = 1; i < ACT; i++)
            if (sa[i] > best) { best = sa[i]; am = i; }
        int m = (am == 0);
        sm_flag = m;
        if (m) { sna[0] = 0.f; sna[1] = 1.f; }
    }
    {
        float* tf = &t[0][0];
        for (int i = tid; i < 34 * 34; i += 256) tf[i] = 0.f;
    }
    __syncthreads();

    float p[9] = {}, pb[9] = {};
    #pragma unroll
    for (int half = 0; half < 2; half++) {
        int j = tid + half * 256;
        float x = bk1[j], xb = x;
        #pragma unroll
        for (int i = 0; i < ACT; i++) {
            float w = Wk1[i * MEM_DIM + j];
            x = fmaf(sa[i], w, x);
            xb = fmaf(sna[i], w, xb);
        }
        x = leakyf(x);
        xb = leakyf(xb);
        #pragma unroll
        for (int tt = 0; tt < 9; tt++) {
            float w = Wk2[j * 9 + tt];
            p[tt] = fmaf(x, w, p[tt]);
            pb[tt] = fmaf(xb, w, pb[tt]);
        }
    }
    float gv = 0.f;
    #pragma unroll
    for (int half = 0; half < 2; half++) {
        int c = tid + half * 256;
        float v = bg1[c];
        #pragma unroll
        for (int ks = 0; ks < KS_G1; ks++)
            v += g_part_g1[((size_t)ks * BS + b) * MEM_DIM + c];
        gv = fmaf(leakyf(v), Wg2[c], gv);
    }

    #pragma unroll
    for (int tt = 0; tt < 9; tt++) {
        #pragma unroll
        for (int o = 16; o > 0; o >>= 1) {
            p[tt] += __shfl_down_sync(0xffffffffu, p[tt], o);
            pb[tt] += __shfl_down_sync(0xffffffffu, pb[tt], o);
        }
    }
    #pragma unroll
    for (int o = 16; o > 0; o >>= 1) gv += __shfl_down_sync(0xffffffffu, gv, o);
    if (lane == 0) {
        #pragma unroll
        for (int tt = 0; tt < 9; tt++) { spart[wid][tt] = p[tt]; spartb[wid][tt] = pb[tt]; }
        sgp[wid] = gv;
    }
    __syncthreads();

    if (tid == 64) {
        float s = bg2[0];
        #pragma unroll
        for (int w = 0; w < 8; w++) s += sgp[w];
        sgate = sigmoidf_(s);
    }
    if (tid == 0) {
        float kkr[9], kkbr[9];
        #pragma unroll
        for (int tt = 0; tt < 9; tt++) {
            float s = bk2[tt], sb = bk2[tt];
            #pragma unroll
            for (int w = 0; w < 8; w++) { s += spart[w][tt]; sb += spartb[w][tt]; }
            kkr[tt] = s; kkbr[tt] = sb;
        }
        int m = sm_flag;
        float v[9];
        #pragma unroll
        for (int i = 0; i < 9; i++) v[i] = m ? kkbr[8 - i] : kkr[i];
        float mx = v[0];
        #pragma unroll
        for (int i = 1; i < 9; i++) mx = fmaxf(mx, v[i]);
        float sum = 0.f;
        #pragma unroll
        for (int i = 0; i < 9; i++) { v[i] = expf(v[i] - mx); sum += v[i]; }
        float inv = 1.f / sum;
        #pragma unroll
        for (int i = 0; i < 9; i++) kk[i] = v[i] * inv;
    }
    __syncthreads();

    for (int i = tid; i < 1024; i += 256)
        t[1 + (i >> 5)][1 + (i & 31)] = prev_alpha[b * 1024 + i];
    __syncthreads();
    float g = sgate;
    for (int i = tid; i < 1024; i += 256) {
        int y = i >> 5, x = i & 31;
        float s = 0.f;
        #pragma unroll
        for (int ky = 0; ky < 3; ky++)
            #pragma unroll
            for (int kx = 0; kx < 3; kx++)
                s = fmaf(t[y + ky][x + kx], kk[ky * 3 + kx], s);
        float pa = t[1 + y][1 + x];
        alpha_out[b * 1024 + i] = s * g + pa * (1.f - g);
    }
}

// ---------------- M update (inline erase/add epilogue) + partial read_v ----
__global__ void mupdate_kernel(const float* __restrict__ M,
                               const float* __restrict__ alpha,
                               const float* __restrict__ bv,
                               float* __restrict__ mnew) {
    int b = blockIdx.y;
    int c = blockIdx.x;
    int d4 = threadIdx.x;        // 0..127
    __shared__ float sal[NCHUNK];
    if (d4 < NCHUNK) sal[d4] = alpha[b * NUM_MEM + c * NCHUNK + d4];

    // reconstruct erase/add for (b, d4) from KS partials (+bias)
    float4 e = *(const float4*)(bv + d4 * 4);
    float4 v = *(const float4*)(bv + MEM_DIM + d4 * 4);
    #pragma unroll
    for (int ks = 0; ks < KS_EA; ks++) {
        float4 pe = ((const float4*)g_part_ea)[((size_t)ks * BS + b) * 256 + d4];
        float4 pv = ((const float4*)g_part_ea)[((size_t)ks * BS + b) * 256 + 128 + d4];
        e.x += pe.x; e.y += pe.y; e.z += pe.z; e.w += pe.w;
        v.x += pv.x; v.y += pv.y; v.z += pv.z; v.w += pv.w;
    }
    e.x = sigmoidf_(e.x); e.y = sigmoidf_(e.y);
    e.z = sigmoidf_(e.z); e.w = sigmoidf_(e.w);
    __syncthreads();

    size_t base = (size_t)b * (NUM_MEM * 128) + (size_t)c * (NCHUNK * 128);
    const float4* Mb = (const float4*)M + base;
    float4* Ob = (float4*)mnew + base;
    float4 rv = make_float4(0.f, 0.f, 0.f, 0.f);

    // explicit batched load phase then compute+store phase
    for (int n0 = 0; n0 < NCHUNK; n0 += MBATCH) {
        float4 m[MBATCH];
        #pragma unroll
        for (int i = 0; i < MBATCH; i++)
            m[i] = __ldcs(&Mb[(n0 + i) * 128 + d4]);
        #pragma unroll
        for (int i = 0; i < MBATCH; i++) {
            float a = sal[n0 + i];
            float4 mn;
            mn.x = fmaf(a, fmaf(-m[i].x, e.x, v.x), m[i].x);
            mn.y = fmaf(a, fmaf(-m[i].y, e.y, v.y), m[i].y);
            mn.z = fmaf(a, fmaf(-m[i].z, e.z, v.z), m[i].z);
            mn.w = fmaf(a, fmaf(-m[i].w, e.w, v.w), m[i].w);
            rv.x = fmaf(a, mn.x, rv.x);
            rv.y = fmaf(a, mn.y, rv.y);
            rv.z = fmaf(a, mn.z, rv.z);
            rv.w = fmaf(a, mn.w, rv.w);
            __stcs(&Ob[(n0 + i) * 128 + d4], mn);
        }
    }
    ((float4*)g_rvpart)[((size_t)c * BS + b) * 128 + d4] = rv;
}

// ---------------- reduce read_v partials (separate kernel: coherent) -------
__global__ void rvreduce_kernel(float* __restrict__ readv) {
    int b = blockIdx.x;
    int d4 = threadIdx.x;  // 128
    float4 s = make_float4(0.f, 0.f, 0.f, 0.f);
    #pragma unroll
    for (int c = 0; c < NSPLIT; c++) {
        float4 p = ((const float4*)g_rvpart)[((size_t)c * BS + b) * 128 + d4];
        s.x += p.x; s.y += p.y; s.z += p.z; s.w += p.w;
    }
    ((float4*)readv)[b * 128 + d4] = s;
}

// ---------------- launch ----------------------------------------------------
extern "C" void kernel_launch(void* const* d_in, const int* in_sizes, int n_in,
                              void* d_out, int out_size) {
    const float* h          = (const float*)d_in[0];
    const float* a          = (const float*)d_in[1];
    const float* prev_alpha = (const float*)d_in[3];
    const float* M          = (const float*)d_in[4];
    const float* Wv         = (const float*)d_in[5];
    const float* bv         = (const float*)d_in[6];
    const float* Wk1        = (const float*)d_in[7];
    const float* bk1        = (const float*)d_in[8];
    const float* Wk2        = (const float*)d_in[9];
    const float* bk2        = (const float*)d_in[10];
    const float* Wg1        = (const float*)d_in[11];
    const float* bg1        = (const float*)d_in[12];
    const float* Wg2        = (const float*)d_in[13];
    const float* bg2        = (const float*)d_in[14];

    float* out = (float*)d_out;
    float* out_readv = out + OUT_READV;
    float* out_other = out + OUT_OTHER;
    float* out_mnew  = out + OUT_MNEW;
    float* out_alpha = out + OUT_ALPHA;

    static cudaStream_t s1 = 0;
    static cudaEvent_t evFork = 0, evJoin = 0, evJoin2 = 0;
    static float *p_ea = 0, *p_g1 = 0, *p_ot = 0;
    static int tried = 0, ok = 0;
    if (!tried) {
        tried = 1;
        ok = (cudaStreamCreateWithFlags(&s1, cudaStreamNonBlocking) == cudaSuccess) &&
             (cudaEventCreateWithFlags(&evFork, cudaEventDisableTiming) == cudaSuccess) &&
             (cudaEventCreateWithFlags(&evJoin, cudaEventDisableTiming) == cudaSuccess) &&
             (cudaEventCreateWithFlags(&evJoin2, cudaEventDisableTiming) == cudaSuccess) &&
             (cudaGetSymbolAddress((void**)&p_ea, g_part_ea) == cudaSuccess) &&
             (cudaGetSymbolAddress((void**)&p_g1, g_part_g1) == cudaSuccess) &&
             (cudaGetSymbolAddress((void**)&p_ot, g_part_ot) == cudaSuccess);
    }
    if (!ok) return;

    // fork
    cudaEventRecord(evFork, 0);
    cudaStreamWaitEvent(s1, evFork, 0);

    // s1: erase/add slab partials (Wv cols 0..1024), KS=2 -> 128 blocks
    gemm_part_kernel<<<dim3(16, 4, KS_EA), 256, 0, s1>>>(
        h, Wv, 3 * MEM_DIM, 0, p_ea, 2 * MEM_DIM, HID / KS_EA);
    cudaEventRecord(evJoin, s1);
    // s1: other_v slab (overlaps conv/mupdate)
    gemm_part_kernel<<<dim3(8, 4, KS_OT), 256, 0, s1>>>(
        h, Wv, 3 * MEM_DIM, 2 * MEM_DIM, p_ot, MEM_DIM, HID / KS_OT);
    epi_other_kernel<<<128, 256, 0, s1>>>(bv, out_other);
    cudaEventRecord(evJoin2, s1);

    // default: g1 gemm partials -> fused kernelnet+gate+conv -> mupdate
    gemm_part_kernel<<<dim3(8, 4, KS_G1), 256>>>(
        h, Wg1, MEM_DIM, 0, p_g1, MEM_DIM, HID / KS_G1);
    conv_fused_kernel<<<BS, 256>>>(a, Wk1, bk1, Wk2, bk2, bg1, Wg2, bg2,
                                   prev_alpha, out_alpha);

    cudaStreamWaitEvent(0, evJoin, 0);
    mupdate_kernel<<<dim3(NSPLIT, BS), 128>>>(M, out_alpha, bv, out_mnew);
    rvreduce_kernel<<<BS, 128>>>(out_readv);
    cudaStreamWaitEvent(0, evJoin2, 0);
}